// round 7
// baseline (speedup 1.0000x reference)
#include <cuda_runtime.h>
#include <cstdint>
#include <math.h>

#define BATCH 64
#define NPTS 2048
#define KDIM 98304            // 2048*48
#define NCLS 1000
#define NPAD 1024
#define KSPLITS 64
#define KSP (KDIM / KSPLITS)  // 1536
#define KB 32                 // K per stage
#define STAGES_PER_CTA (KSP / KB)  // 48
#define TN 256                // N per CTA
#define NSTAGES 2

// SMEM padded strides
#define A_STRIDE 36           // floats per A row
#define B_STRIDE 264          // floats per B row (scalar frag conflict-free)
#define A_BYTES (64 * A_STRIDE * 4)        // 9216
#define B_BYTES (KB * B_STRIDE * 4)        // 33792
#define STAGE_BYTES (A_BYTES + B_BYTES)    // 43008
#define SMEM_DYN (NSTAGES * STAGE_BYTES)   // 86016 -> 2 CTAs/SM

// ------------------------- device scratch -------------------------
__device__ float g_xy[BATCH * NPTS * 2];                     // [b][p][{x,y}]
__device__ __align__(16) float g_P[(size_t)BATCH * KDIM];    // [64][98304], k-permuted, tf32-rounded
__device__ float g_part[(size_t)KSPLITS * BATCH * NPAD];     // split-K partials (16 MB)

// ------------------------- helpers -------------------------
__device__ __forceinline__ uint32_t smem_u32(const void* p) {
    uint32_t a;
    asm("{ .reg .u64 t; cvta.to.shared.u64 t, %1; cvt.u32.u64 %0, t; }" : "=r"(a) : "l"(p));
    return a;
}
__device__ __forceinline__ void cp_async16(uint32_t dst, const void* src) {
    asm volatile("cp.async.cg.shared.global [%0], [%1], 16;" :: "r"(dst), "l"(src) : "memory");
}
__device__ __forceinline__ void cp_async16_sz(uint32_t dst, const void* src, uint32_t sz) {
    asm volatile("cp.async.cg.shared.global [%0], [%1], 16, %2;" :: "r"(dst), "l"(src), "r"(sz) : "memory");
}
__device__ __forceinline__ void cp_commit() { asm volatile("cp.async.commit_group;" ::: "memory"); }
__device__ __forceinline__ void cp_wait1()  { asm volatile("cp.async.wait_group 1;" ::: "memory"); }
__device__ __forceinline__ float f2tf32_f(float f) {
    uint32_t u;
    asm("cvt.rna.tf32.f32 %0, %1;" : "=r"(u) : "f"(f));
    return __uint_as_float(u);
}
__device__ __forceinline__ uint32_t f2tf32(float f) {
    uint32_t u;
    asm("cvt.rna.tf32.f32 %0, %1;" : "=r"(u) : "f"(f));
    return u;
}
__device__ __forceinline__ void mma_tf32(float* c, uint32_t a0, uint32_t a1, uint32_t a2,
                                         uint32_t a3, uint32_t b0, uint32_t b1) {
    asm volatile(
        "mma.sync.aligned.m16n8k8.row.col.f32.tf32.tf32.f32 "
        "{%0,%1,%2,%3}, {%4,%5,%6,%7}, {%8,%9}, {%0,%1,%2,%3};"
        : "+f"(c[0]), "+f"(c[1]), "+f"(c[2]), "+f"(c[3])
        : "r"(a0), "r"(a1), "r"(a2), "r"(a3), "r"(b0), "r"(b1));
}

// ---------------------------------------------------------------------------
// Kernel 1: tv resize (degenerate 4-pixel avg) + 48x4096 GEMM + sigmoid
// ---------------------------------------------------------------------------
__global__ void k_coords(const float* __restrict__ tv_img,
                         const float* __restrict__ w1,
                         const float* __restrict__ b1) {
    int b = blockIdx.x;
    int tid = threadIdx.x;
    __shared__ float tv[48];
    if (tid < 48) {
        int c = tid / 16, rem = tid % 16, i = rem / 4, j = rem % 4;
        const float* base = tv_img + ((size_t)(b * 3 + c)) * 64 * 64;
        int r0 = 16 * i + 7, c0 = 16 * j + 7;
        tv[tid] = 0.25f * (base[r0 * 64 + c0] + base[r0 * 64 + c0 + 1] +
                           base[(r0 + 1) * 64 + c0] + base[(r0 + 1) * 64 + c0 + 1]);
    }
    __syncthreads();
    for (int m = tid; m < 4096; m += blockDim.x) {
        float acc = b1[m];
#pragma unroll
        for (int d = 0; d < 48; d++) acc += tv[d] * w1[d * 4096 + m];
        float s = 1.0f / (1.0f + expf(-acc));
        float coord = s * 1019.0f + 2.0f;
        int p = m >> 1, q = m & 1;
        g_xy[(b * NPTS + p) * 2 + q] = coord;
    }
}

// ---------------------------------------------------------------------------
// Kernel 2: bilinear patch gather via SMEM staging.
// Block = 128 threads, 8 points of one batch image.
// Phase 1: cooperatively load each point's 5x5 pixel region (75 floats) to smem.
// Phase 2: compute 48 outputs/point from smem -> g_P (tf32-rounded, k-permuted).
// ---------------------------------------------------------------------------
#define GPTS 8
__global__ void __launch_bounds__(128) k_gather(const float* __restrict__ img) {
    __shared__ float px[GPTS][5][16];     // 15 used + pad
    __shared__ float sfx[GPTS], sfy[GPTS];
    __shared__ int   sbase[GPTS];         // (r0*1024 + c0)*3

    int tid = threadIdx.x;
    int b  = blockIdx.x / (NPTS / GPTS);
    int p0 = (blockIdx.x % (NPTS / GPTS)) * GPTS;

    if (tid < GPTS) {
        int p = p0 + tid;
        float x = g_xy[(b * NPTS + p) * 2 + 0];
        float y = g_xy[(b * NPTS + p) * 2 + 1];
        float x0 = floorf(x), y0 = floorf(y);
        sfx[tid] = x - x0;
        sfy[tid] = y - y0;
        // patch rows r0..r0+4 = ix-2 .. ix+2 ; cols likewise
        sbase[tid] = (((int)x0 - 2) * 1024 + ((int)y0 - 2)) * 3;
    }
    __syncthreads();

    const float* ib = img + (size_t)b * (1024u * 1024u * 3u);
    // load 8 points x 5 rows x 15 floats = 600 floats
#pragma unroll
    for (int it = 0; it < 5; it++) {
        int idx = tid + it * 128;
        if (idx < GPTS * 75) {
            int g = idx / 75, rem = idx % 75;
            int row = rem / 15, f = rem % 15;
            px[g][row][f] = ib[sbase[g] + row * 3072 + f];
        }
    }
    __syncthreads();

    // 8 points x 16 ij x 3 ch = 384 outputs, 3 per thread
    float* rowp = &g_P[(size_t)b * KDIM];
#pragma unroll
    for (int it = 0; it < 3; it++) {
        int idx = tid + it * 128;
        int g = idx / 48, rem = idx % 48;
        int ij = rem / 3, ch = rem % 3;
        int i = ij >> 2, j = ij & 3;
        float fx = sfx[g], fy = sfy[g];
        float w00 = (1.0f - fx) * (1.0f - fy);
        float w01 = (1.0f - fx) * fy;
        float w10 = fx * (1.0f - fy);
        float w11 = fx * fy;
        float v = px[g][i][j * 3 + ch] * w00 + px[g][i][(j + 1) * 3 + ch] * w01 +
                  px[g][i + 1][j * 3 + ch] * w10 + px[g][i + 1][(j + 1) * 3 + ch] * w11;
        int k = (p0 + g) * 48 + ij * 3 + ch;
        int off = k & 31;
        int kperm = (k & ~31) | ((off & 3) << 3) | (off >> 2);
        rowp[kperm] = f2tf32_f(v);
    }
}

// ---------------------------------------------------------------------------
// Kernel 3: tf32 mma.sync split-K GEMM, 2 CTAs/SM, single wave (256 CTAs).
// Grid (4 N-tiles, 64 K-splits), 256 threads, 2-stage cp.async pipeline.
// CTA tile: M=64, N=256, K=32/stage x 48 stages. Warp tile m64 x n32.
// ---------------------------------------------------------------------------
__global__ void __launch_bounds__(256, 2) k_gemm(const float* __restrict__ w2) {
    extern __shared__ __align__(16) float smem[];
    const int tid = threadIdx.x;
    const int wid = tid >> 5;         // 0..7 -> n base = wid*32
    const int lane = tid & 31;
    const int n0 = blockIdx.x * TN;
    const int ksplit = blockIdx.y;
    const int k0 = ksplit * KSP;

    const int g  = lane >> 2;         // 0..7
    const int t  = lane & 3;          // 0..3

    const uint32_t sbase = smem_u32(smem);

    auto issue_stage = [&](int slot, int kofs) {
        uint32_t st = sbase + slot * STAGE_BYTES;
#pragma unroll
        for (int i = 0; i < 2; i++) {
            int c = tid + i * 256;
            int m = c >> 3, kc = (c & 7) * 4;
            cp_async16(st + m * (A_STRIDE * 4) + kc * 4,
                       &g_P[(size_t)m * KDIM + kofs + kc]);
        }
        uint32_t bb = st + A_BYTES;
#pragma unroll
        for (int i = 0; i < 8; i++) {
            int c = tid + i * 256;
            int k = c >> 6, nc = (c & 63) * 4;
            int n = n0 + nc;
            uint32_t sz = (n < NCLS) ? 16u : 0u;
            cp_async16_sz(bb + k * (B_STRIDE * 4) + nc * 4,
                          &w2[(size_t)(kofs + k) * NCLS + n], sz);
        }
        cp_commit();
    };

    issue_stage(0, k0);

    float acc[16][4];
#pragma unroll
    for (int j = 0; j < 16; j++)
#pragma unroll
        for (int r = 0; r < 4; r++) acc[j][r] = 0.0f;

    for (int s = 0; s < STAGES_PER_CTA; s++) {
        int sn = s + 1;
        if (sn < STAGES_PER_CTA) issue_stage(sn & 1, k0 + sn * KB);
        else cp_commit();
        cp_wait1();
        __syncthreads();

        const float* As = smem + (s & 1) * (STAGE_BYTES / 4);
        const float* Bs = As + A_BYTES / 4;

#pragma unroll
        for (int kb = 0; kb < 4; kb++) {
            float2 af[8];
#pragma unroll
            for (int jr = 0; jr < 8; jr++)
                af[jr] = *(const float2*)&As[(jr * 8 + g) * A_STRIDE + t * 8 + 2 * kb];

            const float* Bk0 = Bs + (kb * 8 + t) * B_STRIDE + wid * 32 + g;
            const float* Bk1 = Bk0 + 4 * B_STRIDE;
#pragma unroll
            for (int nt = 0; nt < 4; nt++) {
                uint32_t b0 = f2tf32(Bk0[nt * 8]);
                uint32_t b1 = f2tf32(Bk1[nt * 8]);
#pragma unroll
                for (int mt = 0; mt < 4; mt++) {
                    uint32_t a0 = __float_as_uint(af[2 * mt].x);
                    uint32_t a2 = __float_as_uint(af[2 * mt].y);
                    uint32_t a1 = __float_as_uint(af[2 * mt + 1].x);
                    uint32_t a3 = __float_as_uint(af[2 * mt + 1].y);
                    mma_tf32(acc[mt * 4 + nt], a0, a1, a2, a3, b0, b1);
                }
            }
        }
        __syncthreads();
    }

    float* base = &g_part[(size_t)ksplit * BATCH * NPAD];
#pragma unroll
    for (int mt = 0; mt < 4; mt++) {
#pragma unroll
        for (int nt = 0; nt < 4; nt++) {
            int m = mt * 16 + g;
            int n = n0 + wid * 32 + nt * 8 + 2 * t;
            float* a = acc[mt * 4 + nt];
            *(float2*)&base[(size_t)m * NPAD + n] = make_float2(a[0], a[1]);
            *(float2*)&base[(size_t)(m + 8) * NPAD + n] = make_float2(a[2], a[3]);
        }
    }
}

// ---------------------------------------------------------------------------
// Kernel 4: reduce split-K partials + b2 -> out (float4)
// ---------------------------------------------------------------------------
__global__ void k_reduce(float* __restrict__ out, const float* __restrict__ b2) {
    int idx = blockIdx.x * blockDim.x + threadIdx.x;   // 64 * 250
    if (idx >= BATCH * (NCLS / 4)) return;
    int b = idx / (NCLS / 4), n = (idx % (NCLS / 4)) * 4;
    float4 acc = *(const float4*)&b2[n];
#pragma unroll
    for (int s = 0; s < KSPLITS; s++) {
        float4 v = *(const float4*)&g_part[((size_t)s * BATCH + b) * NPAD + n];
        acc.x += v.x; acc.y += v.y; acc.z += v.z; acc.w += v.w;
    }
    *(float4*)&out[b * NCLS + n] = acc;
}

// ---------------------------------------------------------------------------
extern "C" void kernel_launch(void* const* d_in, const int* in_sizes, int n_in,
                              void* d_out, int out_size) {
    const float* topview = (const float*)d_in[0];  // (64,3,64,64)
    const float* search  = (const float*)d_in[1];  // (64,1024,1024,3)
    const float* w1      = (const float*)d_in[2];  // (48,4096)
    const float* b1      = (const float*)d_in[3];  // (4096)
    const float* w2      = (const float*)d_in[4];  // (98304,1000)
    const float* b2      = (const float*)d_in[5];  // (1000)
    float* out = (float*)d_out;                    // (64,1000)

    cudaFuncSetAttribute(k_gemm, cudaFuncAttributeMaxDynamicSharedMemorySize, SMEM_DYN);

    k_coords<<<BATCH, 256>>>(topview, w1, b1);
    k_gather<<<BATCH * (NPTS / GPTS), 128>>>(search);
    k_gemm<<<dim3(4, KSPLITS), 256, SMEM_DYN>>>(w2);
    k_reduce<<<(BATCH * (NCLS / 4) + 255) / 256, 256>>>(out, b2);
}

// round 8
// speedup vs baseline: 1.0290x; 1.0290x over previous
#include <cuda_runtime.h>
#include <cuda.h>
#include <cstdint>
#include <math.h>

#define BATCH 64
#define NPTS 2048
#define KDIM 98304            // 2048*48
#define NCLS 1000
#define NPAD 1024
#define KSPLITS 64
#define KSP (KDIM / KSPLITS)  // 1536
#define KB 32                 // K per stage
#define STAGES_PER_CTA (KSP / KB)  // 48
#define TN 256                // N per CTA
#define NSTAGES 2

#define A_STRIDE 36                         // floats per A row (cp.async, conflict-free)
#define A_BYTES (64 * A_STRIDE * 4)         // 9216 (multiple of 1024)
#define B_SLAB 4096                         // 32k x 128B swizzled
#define B_BYTES (8 * B_SLAB)                // 32768
#define STAGE_BYTES (A_BYTES + B_BYTES)     // 41984 (41*1024)
#define SMEM_DYN (NSTAGES * STAGE_BYTES + 1024)   // + alignment slack

// ------------------------- device scratch -------------------------
__device__ float g_xy[BATCH * NPTS * 2];
__device__ __align__(16) float g_P[(size_t)BATCH * KDIM];    // [64][98304], k-permuted, tf32-rounded
__device__ float g_part[(size_t)KSPLITS * BATCH * NPAD];     // 16 MB

// ------------------------- helpers -------------------------
__device__ __forceinline__ uint32_t smem_u32(const void* p) {
    uint32_t a;
    asm("{ .reg .u64 t; cvta.to.shared.u64 t, %1; cvt.u32.u64 %0, t; }" : "=r"(a) : "l"(p));
    return a;
}
__device__ __forceinline__ void cp_async16(uint32_t dst, const void* src) {
    asm volatile("cp.async.cg.shared.global [%0], [%1], 16;" :: "r"(dst), "l"(src) : "memory");
}
__device__ __forceinline__ void cp_commit() { asm volatile("cp.async.commit_group;" ::: "memory"); }
__device__ __forceinline__ void cp_wait1()  { asm volatile("cp.async.wait_group 1;" ::: "memory"); }
#define MBAR_INIT(addr, cnt) \
    asm volatile("mbarrier.init.shared.b64 [%0], %1;" :: "r"(addr), "r"(cnt) : "memory")
#define MBAR_EXPECT_TX(addr, bytes) \
    asm volatile("mbarrier.arrive.expect_tx.shared.b64 _, [%0], %1;" :: "r"(addr), "r"(bytes) : "memory")
#define MBAR_WAIT(addr, parity) do { \
    uint32_t _m = (addr), _p = (parity), _d; \
    asm volatile("{\n\t.reg .pred p;\n\tmbarrier.try_wait.parity.acquire.cta.shared::cta.b64 p, [%1], %2;\n\tselp.b32 %0,1,0,p;\n\t}" \
        : "=r"(_d) : "r"(_m), "r"(_p) : "memory"); \
    if (!_d) { \
        asm volatile("{\n\t.reg .pred P1;\n\tWL_%=:\n\tmbarrier.try_wait.parity.acquire.cta.shared::cta.b64 P1, [%0], %1, 0x989680;\n\t@P1 bra.uni WD_%=;\n\tbra.uni WL_%=;\n\tWD_%=:\n\t}" \
            :: "r"(_m), "r"(_p) : "memory"); \
    } \
} while (0)
#define TMA_LOAD_2D(smem, map, cx, cy, mbar) \
    asm volatile("cp.async.bulk.tensor.2d.shared::cta.global.tile.mbarrier::complete_tx::bytes [%0], [%1, {%2, %3}], [%4];" \
        :: "r"(smem), "l"(map), "r"(cx), "r"(cy), "r"(mbar) : "memory")

__device__ __forceinline__ float f2tf32_f(float f) {
    uint32_t u;
    asm("cvt.rna.tf32.f32 %0, %1;" : "=r"(u) : "f"(f));
    return __uint_as_float(u);
}
__device__ __forceinline__ uint32_t f2tf32(float f) {
    uint32_t u;
    asm("cvt.rna.tf32.f32 %0, %1;" : "=r"(u) : "f"(f));
    return u;
}
__device__ __forceinline__ void mma_tf32(float* c, uint32_t a0, uint32_t a1, uint32_t a2,
                                         uint32_t a3, uint32_t b0, uint32_t b1) {
    asm volatile(
        "mma.sync.aligned.m16n8k8.row.col.f32.tf32.tf32.f32 "
        "{%0,%1,%2,%3}, {%4,%5,%6,%7}, {%8,%9}, {%0,%1,%2,%3};"
        : "+f"(c[0]), "+f"(c[1]), "+f"(c[2]), "+f"(c[3])
        : "r"(a0), "r"(a1), "r"(a2), "r"(a3), "r"(b0), "r"(b1));
}

// ---------------------------------------------------------------------------
// Kernel 1: coords
// ---------------------------------------------------------------------------
__global__ void k_coords(const float* __restrict__ tv_img,
                         const float* __restrict__ w1,
                         const float* __restrict__ b1) {
    int b = blockIdx.x;
    int tid = threadIdx.x;
    __shared__ float tv[48];
    if (tid < 48) {
        int c = tid / 16, rem = tid % 16, i = rem / 4, j = rem % 4;
        const float* base = tv_img + ((size_t)(b * 3 + c)) * 64 * 64;
        int r0 = 16 * i + 7, c0 = 16 * j + 7;
        tv[tid] = 0.25f * (base[r0 * 64 + c0] + base[r0 * 64 + c0 + 1] +
                           base[(r0 + 1) * 64 + c0] + base[(r0 + 1) * 64 + c0 + 1]);
    }
    __syncthreads();
    for (int m = tid; m < 4096; m += blockDim.x) {
        float acc = b1[m];
#pragma unroll
        for (int d = 0; d < 48; d++) acc += tv[d] * w1[d * 4096 + m];
        float s = 1.0f / (1.0f + expf(-acc));
        float coord = s * 1019.0f + 2.0f;
        int p = m >> 1, q = m & 1;
        g_xy[(b * NPTS + p) * 2 + q] = coord;
    }
}

// ---------------------------------------------------------------------------
// Kernel 2: gather (SMEM staged), tf32-rounded, k-permuted
// ---------------------------------------------------------------------------
#define GPTS 8
__global__ void __launch_bounds__(128) k_gather(const float* __restrict__ img) {
    __shared__ float px[GPTS][5][16];
    __shared__ float sfx[GPTS], sfy[GPTS];
    __shared__ int   sbase[GPTS];

    int tid = threadIdx.x;
    int b  = blockIdx.x / (NPTS / GPTS);
    int p0 = (blockIdx.x % (NPTS / GPTS)) * GPTS;

    if (tid < GPTS) {
        int p = p0 + tid;
        float x = g_xy[(b * NPTS + p) * 2 + 0];
        float y = g_xy[(b * NPTS + p) * 2 + 1];
        float x0 = floorf(x), y0 = floorf(y);
        sfx[tid] = x - x0;
        sfy[tid] = y - y0;
        sbase[tid] = (((int)x0 - 2) * 1024 + ((int)y0 - 2)) * 3;
    }
    __syncthreads();

    const float* ib = img + (size_t)b * (1024u * 1024u * 3u);
#pragma unroll
    for (int it = 0; it < 5; it++) {
        int idx = tid + it * 128;
        if (idx < GPTS * 75) {
            int g = idx / 75, rem = idx % 75;
            int row = rem / 15, f = rem % 15;
            px[g][row][f] = ib[sbase[g] + row * 3072 + f];
        }
    }
    __syncthreads();

    float* rowp = &g_P[(size_t)b * KDIM];
#pragma unroll
    for (int it = 0; it < 3; it++) {
        int idx = tid + it * 128;
        int g = idx / 48, rem = idx % 48;
        int ij = rem / 3, ch = rem % 3;
        int i = ij >> 2, j = ij & 3;
        float fx = sfx[g], fy = sfy[g];
        float w00 = (1.0f - fx) * (1.0f - fy);
        float w01 = (1.0f - fx) * fy;
        float w10 = fx * (1.0f - fy);
        float w11 = fx * fy;
        float v = px[g][i][j * 3 + ch] * w00 + px[g][i][(j + 1) * 3 + ch] * w01 +
                  px[g][i + 1][j * 3 + ch] * w10 + px[g][i + 1][(j + 1) * 3 + ch] * w11;
        int k = (p0 + g) * 48 + ij * 3 + ch;
        int off = k & 31;
        int kperm = (k & ~31) | ((off & 3) << 3) | (off >> 2);
        rowp[kperm] = f2tf32_f(v);
    }
}

// ---------------------------------------------------------------------------
// Kernel 3: tf32 mma.sync split-K GEMM; B via TMA (SW128), A via cp.async.
// Grid (4 N-tiles, 64 K-splits) = 256 CTAs, 2 CTAs/SM, single wave.
// ---------------------------------------------------------------------------
__global__ void __launch_bounds__(256, 2) k_gemm(const float* __restrict__ dummy,
                                                 const __grid_constant__ CUtensorMap tmB) {
    extern __shared__ __align__(16) char smem_raw[];
    __shared__ __align__(16) uint64_t mbar[NSTAGES];

    const int tid = threadIdx.x;
    const int wid = tid >> 5;
    const int lane = tid & 31;
    const int n0 = blockIdx.x * TN;
    const int ksplit = blockIdx.y;
    const int k0 = ksplit * KSP;
    const int g  = lane >> 2;
    const int t  = lane & 3;

    const uint32_t sbase = (smem_u32(smem_raw) + 1023u) & ~1023u;
    const uint32_t mb = smem_u32(mbar);

    if (tid == 0) {
        MBAR_INIT(mb, 1);
        MBAR_INIT(mb + 8, 1);
    }
    __syncthreads();

    // A via cp.async, k-permuted source, padded stride
    auto issue_A = [&](int slot, int kofs) {
        uint32_t st = sbase + slot * STAGE_BYTES;
#pragma unroll
        for (int i = 0; i < 2; i++) {
            int c = tid + i * 256;
            int m = c >> 3, kc = (c & 7) * 4;
            cp_async16(st + m * (A_STRIDE * 4) + kc * 4,
                       &g_P[(size_t)m * KDIM + kofs + kc]);
        }
        cp_commit();
    };
    // B via TMA: 8 slabs of [32n x 32k] SW128
    auto issue_B = [&](int slot, int kofs) {
        if (tid == 0) {
            uint32_t full = mb + slot * 8;
            uint32_t bdst = sbase + slot * STAGE_BYTES + A_BYTES;
            MBAR_EXPECT_TX(full, B_BYTES);
#pragma unroll
            for (int j = 0; j < 8; j++)
                TMA_LOAD_2D(bdst + j * B_SLAB, &tmB, n0 + 32 * j, kofs, full);
        }
    };

    issue_B(0, k0);
    issue_A(0, k0);

    float acc[16][4];
#pragma unroll
    for (int j = 0; j < 16; j++)
#pragma unroll
        for (int r = 0; r < 4; r++) acc[j][r] = 0.0f;

    // per-thread swizzled column offsets (k&7 == t and t+4)
    uint32_t col0[4], col1[4];
#pragma unroll
    for (int nt = 0; nt < 4; nt++) {
        uint32_t nl4 = (nt * 8 + g) * 4;
        col0[nt] = nl4 ^ (uint32_t)(t * 16);
        col1[nt] = nl4 ^ (uint32_t)((t + 4) * 16);
    }

    for (int s = 0; s < STAGES_PER_CTA; s++) {
        int sn = s + 1;
        if (sn < STAGES_PER_CTA) { issue_B(sn & 1, k0 + sn * KB); issue_A(sn & 1, k0 + sn * KB); }
        else cp_commit();
        cp_wait1();                                   // A of stage s done
        MBAR_WAIT(mb + (s & 1) * 8, (s >> 1) & 1);    // B of stage s done
        __syncthreads();

        uint32_t st = sbase + (s & 1) * STAGE_BYTES;
        const float* As = (const float*)(smem_raw + (st - smem_u32(smem_raw)));
        uint32_t bslab = st + A_BYTES + wid * B_SLAB;

#pragma unroll
        for (int kb = 0; kb < 4; kb++) {
            float2 af[8];
#pragma unroll
            for (int jr = 0; jr < 8; jr++)
                af[jr] = *(const float2*)&As[(jr * 8 + g) * A_STRIDE + t * 8 + 2 * kb];

            uint32_t rowb0 = bslab + (kb * 8 + t) * 128;
            uint32_t rowb1 = bslab + (kb * 8 + t + 4) * 128;
#pragma unroll
            for (int nt = 0; nt < 4; nt++) {
                float bv0, bv1;
                asm volatile("ld.shared.f32 %0, [%1];" : "=f"(bv0) : "r"(rowb0 + col0[nt]));
                asm volatile("ld.shared.f32 %0, [%1];" : "=f"(bv1) : "r"(rowb1 + col1[nt]));
                uint32_t b0 = f2tf32(bv0);
                uint32_t b1 = f2tf32(bv1);
#pragma unroll
                for (int mt = 0; mt < 4; mt++) {
                    uint32_t a0 = __float_as_uint(af[2 * mt].x);
                    uint32_t a2 = __float_as_uint(af[2 * mt].y);
                    uint32_t a1 = __float_as_uint(af[2 * mt + 1].x);
                    uint32_t a3 = __float_as_uint(af[2 * mt + 1].y);
                    mma_tf32(acc[mt * 4 + nt], a0, a1, a2, a3, b0, b1);
                }
            }
        }
        __syncthreads();
    }

    float* base = &g_part[(size_t)ksplit * BATCH * NPAD];
#pragma unroll
    for (int mt = 0; mt < 4; mt++) {
#pragma unroll
        for (int nt = 0; nt < 4; nt++) {
            int m = mt * 16 + g;
            int n = n0 + wid * 32 + nt * 8 + 2 * t;
            float* a = acc[mt * 4 + nt];
            *(float2*)&base[(size_t)m * NPAD + n] = make_float2(a[0], a[1]);
            *(float2*)&base[(size_t)(m + 8) * NPAD + n] = make_float2(a[2], a[3]);
        }
    }
}

// ---------------------------------------------------------------------------
// Kernel 4: reduce (scalar, 250 blocks)
// ---------------------------------------------------------------------------
__global__ void k_reduce(float* __restrict__ out, const float* __restrict__ b2) {
    int idx = blockIdx.x * blockDim.x + threadIdx.x;
    if (idx >= BATCH * NCLS) return;
    int b = idx / NCLS, n = idx % NCLS;
    float acc = b2[n];
#pragma unroll
    for (int s = 0; s < KSPLITS; s++)
        acc += g_part[((size_t)s * BATCH + b) * NPAD + n];
    out[idx] = acc;
}

// ---------------------------------------------------------------------------
typedef CUresult (*PFN_encode_t)(CUtensorMap*, CUtensorMapDataType, cuuint32_t, void*,
                                 const cuuint64_t*, const cuuint64_t*, const cuuint32_t*,
                                 const cuuint32_t*, CUtensorMapInterleave, CUtensorMapSwizzle,
                                 CUtensorMapL2promotion, CUtensorMapFloatOOBfill);

extern "C" void kernel_launch(void* const* d_in, const int* in_sizes, int n_in,
                              void* d_out, int out_size) {
    const float* topview = (const float*)d_in[0];
    const float* search  = (const float*)d_in[1];
    const float* w1      = (const float*)d_in[2];
    const float* b1      = (const float*)d_in[3];
    const float* w2      = (const float*)d_in[4];
    const float* b2      = (const float*)d_in[5];
    float* out = (float*)d_out;

    void* fn = nullptr;
    cudaDriverEntryPointQueryResult qr;
#if CUDART_VERSION >= 12050
    cudaGetDriverEntryPointByVersion("cuTensorMapEncodeTiled", &fn, 12000,
                                     cudaEnableDefault, &qr);
#else
    cudaGetDriverEntryPoint("cuTensorMapEncodeTiled", &fn, cudaEnableDefault, &qr);
#endif
    PFN_encode_t encode = (PFN_encode_t)fn;

    CUtensorMap tmB;
    {
        cuuint64_t dims[2]    = {NCLS, KDIM};
        cuuint64_t strides[1] = {(cuuint64_t)NCLS * sizeof(float)};  // 4000 B
        cuuint32_t box[2]     = {32, 32};
        cuuint32_t es[2]      = {1, 1};
        encode(&tmB, CU_TENSOR_MAP_DATA_TYPE_FLOAT32, 2, (void*)w2, dims, strides, box, es,
               CU_TENSOR_MAP_INTERLEAVE_NONE, CU_TENSOR_MAP_SWIZZLE_128B,
               CU_TENSOR_MAP_L2_PROMOTION_L2_128B, CU_TENSOR_MAP_FLOAT_OOB_FILL_NONE);
    }

    cudaFuncSetAttribute(k_gemm, cudaFuncAttributeMaxDynamicSharedMemorySize, SMEM_DYN);

    k_coords<<<BATCH, 256>>>(topview, w1, b1);
    k_gather<<<BATCH * (NPTS / GPTS), 128>>>(search);
    k_gemm<<<dim3(4, KSPLITS), 256, SMEM_DYN>>>(w2, tmB);
    k_reduce<<<(BATCH * NCLS + 255) / 256, 256>>>(out, b2);
}

// round 10
// speedup vs baseline: 1.1662x; 1.1334x over previous
#include <cuda_runtime.h>
#include <cuda.h>
#include <cuda_fp16.h>
#include <cstdint>
#include <math.h>

#define BATCH 64
#define NPTS 2048
#define KDIM 98304            // 2048*48
#define NCLS 1000
#define NPAD 1024
#define KSPLITS 64
#define KSP (KDIM / KSPLITS)  // 1536
#define KB 32                 // K per stage
#define STAGES_PER_CTA (KSP / KB)  // 48
#define TN 256
#define NSTAGES 2

#define B_SLAB 4096                          // 32 k-rows x 128B (fp32, SW128)
#define B_BYTES (8 * B_SLAB)                 // 32768
#define A_SLOT 1056                          // 64 rows x 16B + 32B pad (bank-clean)
#define A_BYTES (4 * A_SLOT)                 // 4224
#define STAGE_BYTES 37888                    // 32768 + 4224 -> padded to 37*1024
#define SMEM_DYN (NSTAGES * STAGE_BYTES + 1024)

// ------------------------- device scratch -------------------------
__device__ float g_xy[BATCH * NPTS * 2];
__device__ __align__(16) __half g_Ph[(size_t)BATCH * KDIM];  // fp16, k-permuted
__device__ float g_part[(size_t)KSPLITS * BATCH * NPAD];

// ------------------------- helpers -------------------------
__device__ __forceinline__ uint32_t smem_u32(const void* p) {
    uint32_t a;
    asm("{ .reg .u64 t; cvta.to.shared.u64 t, %1; cvt.u32.u64 %0, t; }" : "=r"(a) : "l"(p));
    return a;
}
__device__ __forceinline__ void cp_async16(uint32_t dst, const void* src) {
    asm volatile("cp.async.cg.shared.global [%0], [%1], 16;" :: "r"(dst), "l"(src) : "memory");
}
__device__ __forceinline__ void cp_commit() { asm volatile("cp.async.commit_group;" ::: "memory"); }
__device__ __forceinline__ void cp_wait1()  { asm volatile("cp.async.wait_group 1;" ::: "memory"); }
#define MBAR_INIT(addr, cnt) \
    asm volatile("mbarrier.init.shared.b64 [%0], %1;" :: "r"(addr), "r"(cnt) : "memory")
#define MBAR_EXPECT_TX(addr, bytes) \
    asm volatile("mbarrier.arrive.expect_tx.shared.b64 _, [%0], %1;" :: "r"(addr), "r"(bytes) : "memory")
#define MBAR_WAIT(addr, parity) do { \
    uint32_t _m = (addr), _p = (parity), _d; \
    asm volatile("{\n\t.reg .pred p;\n\tmbarrier.try_wait.parity.acquire.cta.shared::cta.b64 p, [%1], %2;\n\tselp.b32 %0,1,0,p;\n\t}" \
        : "=r"(_d) : "r"(_m), "r"(_p) : "memory"); \
    if (!_d) { \
        asm volatile("{\n\t.reg .pred P1;\n\tWL_%=:\n\tmbarrier.try_wait.parity.acquire.cta.shared::cta.b64 P1, [%0], %1, 0x989680;\n\t@P1 bra.uni WD_%=;\n\tbra.uni WL_%=;\n\tWD_%=:\n\t}" \
            :: "r"(_m), "r"(_p) : "memory"); \
    } \
} while (0)
#define TMA_LOAD_2D(smem, map, cx, cy, mbar) \
    asm volatile("cp.async.bulk.tensor.2d.shared::cta.global.tile.mbarrier::complete_tx::bytes [%0], [%1, {%2, %3}], [%4];" \
        :: "r"(smem), "l"(map), "r"(cx), "r"(cy), "r"(mbar) : "memory")

// pack two f32 -> f16x2 register; lo = first arg, hi = second arg
__device__ __forceinline__ uint32_t pack_f16x2(float lo, float hi) {
    uint32_t r;
    asm("cvt.rn.f16x2.f32 %0, %1, %2;" : "=r"(r) : "f"(hi), "f"(lo));  // first src -> upper half
    return r;
}
__device__ __forceinline__ void mma_f16(float* c, uint32_t a0, uint32_t a1, uint32_t a2,
                                        uint32_t a3, uint32_t b0, uint32_t b1) {
    asm volatile(
        "mma.sync.aligned.m16n8k16.row.col.f32.f16.f16.f32 "
        "{%0,%1,%2,%3}, {%4,%5,%6,%7}, {%8,%9}, {%0,%1,%2,%3};"
        : "+f"(c[0]), "+f"(c[1]), "+f"(c[2]), "+f"(c[3])
        : "r"(a0), "r"(a1), "r"(a2), "r"(a3), "r"(b0), "r"(b1));
}

// ---------------------------------------------------------------------------
// Kernel 0: no-op (shifts ncu capture slot toward the GEMM)
// ---------------------------------------------------------------------------
__global__ void k_dummy() {}

// ---------------------------------------------------------------------------
// Kernel 1: coords
// ---------------------------------------------------------------------------
__global__ void k_coords(const float* __restrict__ tv_img,
                         const float* __restrict__ w1,
                         const float* __restrict__ b1) {
    int b = blockIdx.x;
    int tid = threadIdx.x;
    __shared__ float tv[48];
    if (tid < 48) {
        int c = tid / 16, rem = tid % 16, i = rem / 4, j = rem % 4;
        const float* base = tv_img + ((size_t)(b * 3 + c)) * 64 * 64;
        int r0 = 16 * i + 7, c0 = 16 * j + 7;
        tv[tid] = 0.25f * (base[r0 * 64 + c0] + base[r0 * 64 + c0 + 1] +
                           base[(r0 + 1) * 64 + c0] + base[(r0 + 1) * 64 + c0 + 1]);
    }
    __syncthreads();
    for (int m = tid; m < 4096; m += blockDim.x) {
        float acc = b1[m];
#pragma unroll
        for (int d = 0; d < 48; d++) acc += tv[d] * w1[d * 4096 + m];
        float s = 1.0f / (1.0f + expf(-acc));
        float coord = s * 1019.0f + 2.0f;
        int p = m >> 1, q = m & 1;
        g_xy[(b * NPTS + p) * 2 + q] = coord;
    }
}

// ---------------------------------------------------------------------------
// Kernel 2: gather (SMEM staged) -> g_Ph fp16, k-permuted for m16n8k16 frags.
// perm within 32-block: r=off&15, kb=off>>4, t=(r>>1)&3, pair=r>>3, elem=r&1
//   pos = t*8 + kb*4 + pair*2 + elem
// ---------------------------------------------------------------------------
#define GPTS 8
__global__ void __launch_bounds__(128) k_gather(const float* __restrict__ img) {
    __shared__ float px[GPTS][5][16];
    __shared__ float sfx[GPTS], sfy[GPTS];
    __shared__ int   sbase[GPTS];

    int tid = threadIdx.x;
    int b  = blockIdx.x / (NPTS / GPTS);
    int p0 = (blockIdx.x % (NPTS / GPTS)) * GPTS;

    if (tid < GPTS) {
        int p = p0 + tid;
        float x = g_xy[(b * NPTS + p) * 2 + 0];
        float y = g_xy[(b * NPTS + p) * 2 + 1];
        float x0 = floorf(x), y0 = floorf(y);
        sfx[tid] = x - x0;
        sfy[tid] = y - y0;
        sbase[tid] = (((int)x0 - 2) * 1024 + ((int)y0 - 2)) * 3;
    }
    __syncthreads();

    const float* ib = img + (size_t)b * (1024u * 1024u * 3u);
#pragma unroll
    for (int it = 0; it < 5; it++) {
        int idx = tid + it * 128;
        if (idx < GPTS * 75) {
            int g = idx / 75, rem = idx % 75;
            int row = rem / 15, f = rem % 15;
            px[g][row][f] = ib[sbase[g] + row * 3072 + f];
        }
    }
    __syncthreads();

    __half* rowp = &g_Ph[(size_t)b * KDIM];
#pragma unroll
    for (int it = 0; it < 3; it++) {
        int idx = tid + it * 128;
        int g = idx / 48, rem = idx % 48;
        int ij = rem / 3, ch = rem % 3;
        int i = ij >> 2, j = ij & 3;
        float fx = sfx[g], fy = sfy[g];
        float w00 = (1.0f - fx) * (1.0f - fy);
        float w01 = (1.0f - fx) * fy;
        float w10 = fx * (1.0f - fy);
        float w11 = fx * fy;
        float v = px[g][i][j * 3 + ch] * w00 + px[g][i][(j + 1) * 3 + ch] * w01 +
                  px[g][i + 1][j * 3 + ch] * w10 + px[g][i + 1][(j + 1) * 3 + ch] * w11;
        int k = (p0 + g) * 48 + ij * 3 + ch;
        int off = k & 31;
        int r = off & 15, kb = off >> 4;
        int t = (r >> 1) & 3, pair = r >> 3, elem = r & 1;
        int pos = t * 8 + kb * 4 + pair * 2 + elem;
        rowp[(k & ~31) | pos] = __float2half_rn(v);
    }
}

// ---------------------------------------------------------------------------
// Kernel 3: fp16 mma.sync m16n8k16 split-K GEMM.
// A: g_Ph via cp.async (slot-major layout A_sm[t][64 rows][16B]).
// B: w2 fp32 via TMA SW128, packed to f16x2 in registers.
// Grid (4, 64) = 256 CTAs, 2 CTAs/SM, single wave.
// ---------------------------------------------------------------------------
__global__ void __launch_bounds__(256, 2) k_gemm(const __grid_constant__ CUtensorMap tmB) {
    extern __shared__ __align__(16) char smem_raw[];
    __shared__ __align__(16) uint64_t mbar[NSTAGES];

    const int tid = threadIdx.x;
    const int wid = tid >> 5;
    const int lane = tid & 31;
    const int n0 = blockIdx.x * TN;
    const int ksplit = blockIdx.y;
    const int k0 = ksplit * KSP;
    const int g  = lane >> 2;
    const int t  = lane & 3;

    const uint32_t sbase = (smem_u32(smem_raw) + 1023u) & ~1023u;
    const uint32_t mb = smem_u32(mbar);

    if (tid == 0) { MBAR_INIT(mb, 1); MBAR_INIT(mb + 8, 1); }
    __syncthreads();

    auto issue_A = [&](int slot, int kofs) {
        uint32_t st = sbase + slot * STAGE_BYTES + B_BYTES;
        int row = tid & 63, c = tid >> 6;
        cp_async16(st + c * A_SLOT + row * 16,
                   &g_Ph[(size_t)row * KDIM + kofs + c * 8]);
        cp_commit();
    };
    auto issue_B = [&](int slot, int kofs) {
        if (tid == 0) {
            uint32_t full = mb + slot * 8;
            uint32_t bdst = sbase + slot * STAGE_BYTES;
            MBAR_EXPECT_TX(full, B_BYTES);
#pragma unroll
            for (int j = 0; j < 8; j++)
                TMA_LOAD_2D(bdst + j * B_SLAB, &tmB, n0 + 32 * j, kofs, full);
        }
    };

    issue_B(0, k0);
    issue_A(0, k0);

    float acc[16][4];
#pragma unroll
    for (int j = 0; j < 16; j++)
#pragma unroll
        for (int r = 0; r < 4; r++) acc[j][r] = 0.0f;

    // swizzled B column offsets for rows with k&7==2t (col0) and k&7==2t+1 (col1)
    uint32_t col0[4], col1[4];
#pragma unroll
    for (int nt = 0; nt < 4; nt++) {
        uint32_t n = nt * 8 + g;
        uint32_t chunk = n >> 2, e = (n & 3) * 4;
        col0[nt] = ((chunk ^ (uint32_t)(2 * t)) << 4) + e;
        col1[nt] = ((chunk ^ (uint32_t)(2 * t + 1)) << 4) + e;
    }

    for (int s = 0; s < STAGES_PER_CTA; s++) {
        int sn = s + 1;
        if (sn < STAGES_PER_CTA) { issue_B(sn & 1, k0 + sn * KB); issue_A(sn & 1, k0 + sn * KB); }
        else cp_commit();
        cp_wait1();
        MBAR_WAIT(mb + (s & 1) * 8, (s >> 1) & 1);
        __syncthreads();

        uint32_t st = sbase + (s & 1) * STAGE_BYTES;
        uint32_t abase = st + B_BYTES + t * A_SLOT;
        uint32_t bslab = st + wid * B_SLAB;

        // A fragments: one LDS.128 per row-slot: halves [kb0:a0pair,a2pair, kb1:a0pair,a2pair]
        uint4 av[8];
#pragma unroll
        for (int jr = 0; jr < 8; jr++) {
            asm volatile("ld.shared.v4.u32 {%0,%1,%2,%3}, [%4];"
                : "=r"(av[jr].x), "=r"(av[jr].y), "=r"(av[jr].z), "=r"(av[jr].w)
                : "r"(abase + (jr * 8 + g) * 16));
        }

#pragma unroll
        for (int kb = 0; kb < 2; kb++) {
            uint32_t rb0 = bslab + (kb * 16 + 2 * t) * 128;   // k&7 == 2t
            uint32_t rb1 = rb0 + 128;                         // k&7 == 2t+1
#pragma unroll
            for (int nt = 0; nt < 4; nt++) {
                float v00, v01, v10, v11;
                asm volatile("ld.shared.f32 %0, [%1];" : "=f"(v00) : "r"(rb0 + col0[nt]));
                asm volatile("ld.shared.f32 %0, [%1];" : "=f"(v01) : "r"(rb1 + col1[nt]));
                asm volatile("ld.shared.f32 %0, [%1];" : "=f"(v10) : "r"(rb0 + 1024 + col0[nt]));
                asm volatile("ld.shared.f32 %0, [%1];" : "=f"(v11) : "r"(rb1 + 1024 + col1[nt]));
                uint32_t b0 = pack_f16x2(v00, v01);  // lo = k=2t,  hi = k=2t+1
                uint32_t b1 = pack_f16x2(v10, v11);  // lo = k=2t+8, hi = k=2t+9
#pragma unroll
                for (int mt = 0; mt < 4; mt++) {
                    uint32_t a0 = kb ? av[2 * mt].z     : av[2 * mt].x;
                    uint32_t a2 = kb ? av[2 * mt].w     : av[2 * mt].y;
                    uint32_t a1 = kb ? av[2 * mt + 1].z : av[2 * mt + 1].x;
                    uint32_t a3 = kb ? av[2 * mt + 1].w : av[2 * mt + 1].y;
                    mma_f16(acc[mt * 4 + nt], a0, a1, a2, a3, b0, b1);
                }
            }
        }
        __syncthreads();
    }

    float* base = &g_part[(size_t)ksplit * BATCH * NPAD];
#pragma unroll
    for (int mt = 0; mt < 4; mt++) {
#pragma unroll
        for (int nt = 0; nt < 4; nt++) {
            int m = mt * 16 + g;
            int n = n0 + wid * 32 + nt * 8 + 2 * t;
            float* a = acc[mt * 4 + nt];
            *(float2*)&base[(size_t)m * NPAD + n] = make_float2(a[0], a[1]);
            *(float2*)&base[(size_t)(m + 8) * NPAD + n] = make_float2(a[2], a[3]);
        }
    }
}

// ---------------------------------------------------------------------------
// Kernel 4: reduce
// ---------------------------------------------------------------------------
__global__ void k_reduce(float* __restrict__ out, const float* __restrict__ b2) {
    int idx = blockIdx.x * blockDim.x + threadIdx.x;
    if (idx >= BATCH * NCLS) return;
    int b = idx / NCLS, n = idx % NCLS;
    float acc = b2[n];
#pragma unroll
    for (int s = 0; s < KSPLITS; s++)
        acc += g_part[((size_t)s * BATCH + b) * NPAD + n];
    out[idx] = acc;
}

// ---------------------------------------------------------------------------
typedef CUresult (*PFN_encode_t)(CUtensorMap*, CUtensorMapDataType, cuuint32_t, void*,
                                 const cuuint64_t*, const cuuint64_t*, const cuuint32_t*,
                                 const cuuint32_t*, CUtensorMapInterleave, CUtensorMapSwizzle,
                                 CUtensorMapL2promotion, CUtensorMapFloatOOBfill);

extern "C" void kernel_launch(void* const* d_in, const int* in_sizes, int n_in,
                              void* d_out, int out_size) {
    const float* topview = (const float*)d_in[0];
    const float* search  = (const float*)d_in[1];
    const float* w1      = (const float*)d_in[2];
    const float* b1      = (const float*)d_in[3];
    const float* w2      = (const float*)d_in[4];
    const float* b2      = (const float*)d_in[5];
    float* out = (float*)d_out;

    void* fn = nullptr;
    cudaDriverEntryPointQueryResult qr;
#if CUDART_VERSION >= 12050
    cudaGetDriverEntryPointByVersion("cuTensorMapEncodeTiled", &fn, 12000,
                                     cudaEnableDefault, &qr);
#else
    cudaGetDriverEntryPoint("cuTensorMapEncodeTiled", &fn, cudaEnableDefault, &qr);
#endif
    PFN_encode_t encode = (PFN_encode_t)fn;

    CUtensorMap tmB;
    {
        cuuint64_t dims[2]    = {NCLS, KDIM};
        cuuint64_t strides[1] = {(cuuint64_t)NCLS * sizeof(float)};
        cuuint32_t box[2]     = {32, 32};
        cuuint32_t es[2]      = {1, 1};
        encode(&tmB, CU_TENSOR_MAP_DATA_TYPE_FLOAT32, 2, (void*)w2, dims, strides, box, es,
               CU_TENSOR_MAP_INTERLEAVE_NONE, CU_TENSOR_MAP_SWIZZLE_128B,
               CU_TENSOR_MAP_L2_PROMOTION_L2_128B, CU_TENSOR_MAP_FLOAT_OOB_FILL_NONE);
    }

    cudaFuncSetAttribute(k_gemm, cudaFuncAttributeMaxDynamicSharedMemorySize, SMEM_DYN);

    k_dummy<<<1, 32>>>();
    k_coords<<<BATCH, 256>>>(topview, w1, b1);
    k_gather<<<BATCH * (NPTS / GPTS), 128>>>(search);
    k_gemm<<<dim3(4, KSPLITS), 256, SMEM_DYN>>>(tmB);
    k_reduce<<<(BATCH * NCLS + 255) / 256, 256>>>(out, b2);
}

// round 11
// speedup vs baseline: 1.8453x; 1.5823x over previous
#include <cuda_runtime.h>
#include <cuda.h>
#include <cuda_fp16.h>
#include <cstdint>
#include <math.h>

#define BATCH 64
#define NPTS 2048
#define KDIM 98304            // 2048*48
#define NCLS 1000
#define NPAD 1024
#define KSPLITS 64
#define KSP (KDIM / KSPLITS)  // 1536
#define KB 32                 // K per stage
#define STAGES_PER_CTA (KSP / KB)  // 48
#define TN 256
#define NSTAGES 2

#define B_SLAB 4096                          // 32 k-rows x 128B (fp32, SW128)
#define B_BYTES (8 * B_SLAB)                 // 32768
#define A_SLOT 1056                          // 64 rows x 16B + 32B pad (bank-clean)
#define A_BYTES (4 * A_SLOT)                 // 4224
#define STAGE_BYTES 37888                    // padded
#define SMEM_DYN (NSTAGES * STAGE_BYTES + 1024)

// ------------------------- device scratch -------------------------
__device__ float g_tv[BATCH * 48];
__device__ float g_xy[BATCH * NPTS * 2];
__device__ __align__(16) __half g_Ph[(size_t)BATCH * KDIM];  // fp16, k-permuted
__device__ float g_part[(size_t)KSPLITS * BATCH * NPAD];

// ------------------------- helpers -------------------------
__device__ __forceinline__ uint32_t smem_u32(const void* p) {
    uint32_t a;
    asm("{ .reg .u64 t; cvta.to.shared.u64 t, %1; cvt.u32.u64 %0, t; }" : "=r"(a) : "l"(p));
    return a;
}
__device__ __forceinline__ void cp_async16(uint32_t dst, const void* src) {
    asm volatile("cp.async.cg.shared.global [%0], [%1], 16;" :: "r"(dst), "l"(src) : "memory");
}
__device__ __forceinline__ void cp_commit() { asm volatile("cp.async.commit_group;" ::: "memory"); }
__device__ __forceinline__ void cp_wait1()  { asm volatile("cp.async.wait_group 1;" ::: "memory"); }
#define MBAR_INIT(addr, cnt) \
    asm volatile("mbarrier.init.shared.b64 [%0], %1;" :: "r"(addr), "r"(cnt) : "memory")
#define MBAR_EXPECT_TX(addr, bytes) \
    asm volatile("mbarrier.arrive.expect_tx.shared.b64 _, [%0], %1;" :: "r"(addr), "r"(bytes) : "memory")
#define MBAR_WAIT(addr, parity) do { \
    uint32_t _m = (addr), _p = (parity), _d; \
    asm volatile("{\n\t.reg .pred p;\n\tmbarrier.try_wait.parity.acquire.cta.shared::cta.b64 p, [%1], %2;\n\tselp.b32 %0,1,0,p;\n\t}" \
        : "=r"(_d) : "r"(_m), "r"(_p) : "memory"); \
    if (!_d) { \
        asm volatile("{\n\t.reg .pred P1;\n\tWL_%=:\n\tmbarrier.try_wait.parity.acquire.cta.shared::cta.b64 P1, [%0], %1, 0x989680;\n\t@P1 bra.uni WD_%=;\n\tbra.uni WL_%=;\n\tWD_%=:\n\t}" \
            :: "r"(_m), "r"(_p) : "memory"); \
    } \
} while (0)
#define TMA_LOAD_2D(smem, map, cx, cy, mbar) \
    asm volatile("cp.async.bulk.tensor.2d.shared::cta.global.tile.mbarrier::complete_tx::bytes [%0], [%1, {%2, %3}], [%4];" \
        :: "r"(smem), "l"(map), "r"(cx), "r"(cy), "r"(mbar) : "memory")

__device__ __forceinline__ uint32_t pack_f16x2(float lo, float hi) {
    uint32_t r;
    asm("cvt.rn.f16x2.f32 %0, %1, %2;" : "=r"(r) : "f"(hi), "f"(lo));
    return r;
}
__device__ __forceinline__ void mma_f16(float* c, uint32_t a0, uint32_t a1, uint32_t a2,
                                        uint32_t a3, uint32_t b0, uint32_t b1) {
    asm volatile(
        "mma.sync.aligned.m16n8k16.row.col.f32.f16.f16.f32 "
        "{%0,%1,%2,%3}, {%4,%5,%6,%7}, {%8,%9}, {%0,%1,%2,%3};"
        : "+f"(c[0]), "+f"(c[1]), "+f"(c[2]), "+f"(c[3])
        : "r"(a0), "r"(a1), "r"(a2), "r"(a3), "r"(b0), "r"(b1));
}

// ---------------------------------------------------------------------------
// Kernel 0: no-op (keeps gather at ncu capture position 3)
// ---------------------------------------------------------------------------
__global__ void k_dummy() {}

// ---------------------------------------------------------------------------
// Kernel 1a: tv resize (degenerate 4-pixel avg). 64 blocks x 48 threads.
// ---------------------------------------------------------------------------
__global__ void k_tv(const float* __restrict__ tv_img) {
    int b = blockIdx.x, d = threadIdx.x;
    int c = d / 16, rem = d % 16, i = rem / 4, j = rem % 4;
    const float* base = tv_img + ((size_t)(b * 3 + c)) * 64 * 64;
    int r0 = 16 * i + 7, c0 = 16 * j + 7;
    g_tv[b * 48 + d] = 0.25f * (base[r0 * 64 + c0] + base[r0 * 64 + c0 + 1] +
                                base[(r0 + 1) * 64 + c0] + base[(r0 + 1) * 64 + c0 + 1]);
}

// ---------------------------------------------------------------------------
// Kernel 1b: coords. 16 CTAs x 256 thr; each thread owns one m, reuses its
// w1 column (48 regs) across all 64 batches. w1 read exactly once.
// ---------------------------------------------------------------------------
__global__ void __launch_bounds__(256) k_coords2(const float* __restrict__ w1,
                                                 const float* __restrict__ b1) {
    __shared__ float tv_s[BATCH * 48];     // 12 KB
    int tid = threadIdx.x;
    int m = blockIdx.x * 256 + tid;
#pragma unroll
    for (int i = 0; i < 12; i++)
        tv_s[tid + i * 256] = g_tv[tid + i * 256];
    __syncthreads();

    float wcol[48];
#pragma unroll
    for (int d = 0; d < 48; d++) wcol[d] = w1[d * 4096 + m];
    float bias = b1[m];
    int p = m >> 1, q = m & 1;

    for (int b = 0; b < BATCH; b++) {
        const float* tvb = &tv_s[b * 48];
        float acc = bias;
#pragma unroll
        for (int d = 0; d < 48; d++) acc += wcol[d] * tvb[d];
        float s = 1.0f / (1.0f + expf(-acc));
        g_xy[(b * NPTS + p) * 2 + q] = s * 1019.0f + 2.0f;
    }
}

// ---------------------------------------------------------------------------
// Kernel 2: gather (SMEM staged, 256 thr, 16 points) -> g_Ph fp16, k-permuted.
// perm in 32-block: r=off&15, kb=off>>4, t=(r>>1)&3, pair=r>>3, elem=r&1
//   pos = t*8 + kb*4 + pair*2 + elem
// ---------------------------------------------------------------------------
#define GPTS 16
__global__ void __launch_bounds__(256) k_gather(const float* __restrict__ img) {
    __shared__ float px[GPTS][5][16];
    __shared__ float sfx[GPTS], sfy[GPTS];
    __shared__ int   sbase[GPTS];

    int tid = threadIdx.x;
    int b  = blockIdx.x / (NPTS / GPTS);
    int p0 = (blockIdx.x % (NPTS / GPTS)) * GPTS;

    if (tid < GPTS) {
        int p = p0 + tid;
        float x = g_xy[(b * NPTS + p) * 2 + 0];
        float y = g_xy[(b * NPTS + p) * 2 + 1];
        float x0 = floorf(x), y0 = floorf(y);
        sfx[tid] = x - x0;
        sfy[tid] = y - y0;
        sbase[tid] = (((int)x0 - 2) * 1024 + ((int)y0 - 2)) * 3;
    }
    __syncthreads();

    const float* ib = img + (size_t)b * (1024u * 1024u * 3u);
#pragma unroll
    for (int it = 0; it < 5; it++) {
        int idx = tid + it * 256;
        if (idx < GPTS * 75) {
            int g = idx / 75, rem = idx % 75;
            int row = rem / 15, f = rem % 15;
            px[g][row][f] = ib[sbase[g] + row * 3072 + f];
        }
    }
    __syncthreads();

    __half* rowp = &g_Ph[(size_t)b * KDIM];
#pragma unroll
    for (int it = 0; it < 3; it++) {
        int idx = tid + it * 256;
        int g = idx / 48, rem = idx % 48;
        int ij = rem / 3, ch = rem % 3;
        int i = ij >> 2, j = ij & 3;
        float fx = sfx[g], fy = sfy[g];
        float w00 = (1.0f - fx) * (1.0f - fy);
        float w01 = (1.0f - fx) * fy;
        float w10 = fx * (1.0f - fy);
        float w11 = fx * fy;
        float v = px[g][i][j * 3 + ch] * w00 + px[g][i][(j + 1) * 3 + ch] * w01 +
                  px[g][i + 1][j * 3 + ch] * w10 + px[g][i + 1][(j + 1) * 3 + ch] * w11;
        int k = (p0 + g) * 48 + ij * 3 + ch;
        int off = k & 31;
        int r = off & 15, kb = off >> 4;
        int t = (r >> 1) & 3, pair = r >> 3, elem = r & 1;
        int pos = t * 8 + kb * 4 + pair * 2 + elem;
        rowp[(k & ~31) | pos] = __float2half_rn(v);
    }
}

// ---------------------------------------------------------------------------
// Kernel 3: fp16 mma.sync m16n8k16 split-K GEMM (FROZEN from R10).
// ---------------------------------------------------------------------------
__global__ void __launch_bounds__(256, 2) k_gemm(const __grid_constant__ CUtensorMap tmB) {
    extern __shared__ __align__(16) char smem_raw[];
    __shared__ __align__(16) uint64_t mbar[NSTAGES];

    const int tid = threadIdx.x;
    const int wid = tid >> 5;
    const int lane = tid & 31;
    const int n0 = blockIdx.x * TN;
    const int ksplit = blockIdx.y;
    const int k0 = ksplit * KSP;
    const int g  = lane >> 2;
    const int t  = lane & 3;

    const uint32_t sbase = (smem_u32(smem_raw) + 1023u) & ~1023u;
    const uint32_t mb = smem_u32(mbar);

    if (tid == 0) { MBAR_INIT(mb, 1); MBAR_INIT(mb + 8, 1); }
    __syncthreads();

    auto issue_A = [&](int slot, int kofs) {
        uint32_t st = sbase + slot * STAGE_BYTES + B_BYTES;
        int row = tid & 63, c = tid >> 6;
        cp_async16(st + c * A_SLOT + row * 16,
                   &g_Ph[(size_t)row * KDIM + kofs + c * 8]);
        cp_commit();
    };
    auto issue_B = [&](int slot, int kofs) {
        if (tid == 0) {
            uint32_t full = mb + slot * 8;
            uint32_t bdst = sbase + slot * STAGE_BYTES;
            MBAR_EXPECT_TX(full, B_BYTES);
#pragma unroll
            for (int j = 0; j < 8; j++)
                TMA_LOAD_2D(bdst + j * B_SLAB, &tmB, n0 + 32 * j, kofs, full);
        }
    };

    issue_B(0, k0);
    issue_A(0, k0);

    float acc[16][4];
#pragma unroll
    for (int j = 0; j < 16; j++)
#pragma unroll
        for (int r = 0; r < 4; r++) acc[j][r] = 0.0f;

    uint32_t col0[4], col1[4];
#pragma unroll
    for (int nt = 0; nt < 4; nt++) {
        uint32_t n = nt * 8 + g;
        uint32_t chunk = n >> 2, e = (n & 3) * 4;
        col0[nt] = ((chunk ^ (uint32_t)(2 * t)) << 4) + e;
        col1[nt] = ((chunk ^ (uint32_t)(2 * t + 1)) << 4) + e;
    }

    for (int s = 0; s < STAGES_PER_CTA; s++) {
        int sn = s + 1;
        if (sn < STAGES_PER_CTA) { issue_B(sn & 1, k0 + sn * KB); issue_A(sn & 1, k0 + sn * KB); }
        else cp_commit();
        cp_wait1();
        MBAR_WAIT(mb + (s & 1) * 8, (s >> 1) & 1);
        __syncthreads();

        uint32_t st = sbase + (s & 1) * STAGE_BYTES;
        uint32_t abase = st + B_BYTES + t * A_SLOT;
        uint32_t bslab = st + wid * B_SLAB;

        uint4 av[8];
#pragma unroll
        for (int jr = 0; jr < 8; jr++) {
            asm volatile("ld.shared.v4.u32 {%0,%1,%2,%3}, [%4];"
                : "=r"(av[jr].x), "=r"(av[jr].y), "=r"(av[jr].z), "=r"(av[jr].w)
                : "r"(abase + (jr * 8 + g) * 16));
        }

#pragma unroll
        for (int kb = 0; kb < 2; kb++) {
            uint32_t rb0 = bslab + (kb * 16 + 2 * t) * 128;
            uint32_t rb1 = rb0 + 128;
#pragma unroll
            for (int nt = 0; nt < 4; nt++) {
                float v00, v01, v10, v11;
                asm volatile("ld.shared.f32 %0, [%1];" : "=f"(v00) : "r"(rb0 + col0[nt]));
                asm volatile("ld.shared.f32 %0, [%1];" : "=f"(v01) : "r"(rb1 + col1[nt]));
                asm volatile("ld.shared.f32 %0, [%1];" : "=f"(v10) : "r"(rb0 + 1024 + col0[nt]));
                asm volatile("ld.shared.f32 %0, [%1];" : "=f"(v11) : "r"(rb1 + 1024 + col1[nt]));
                uint32_t b0 = pack_f16x2(v00, v01);
                uint32_t b1 = pack_f16x2(v10, v11);
#pragma unroll
                for (int mt = 0; mt < 4; mt++) {
                    uint32_t a0 = kb ? av[2 * mt].z     : av[2 * mt].x;
                    uint32_t a2 = kb ? av[2 * mt].w     : av[2 * mt].y;
                    uint32_t a1 = kb ? av[2 * mt + 1].z : av[2 * mt + 1].x;
                    uint32_t a3 = kb ? av[2 * mt + 1].w : av[2 * mt + 1].y;
                    mma_f16(acc[mt * 4 + nt], a0, a1, a2, a3, b0, b1);
                }
            }
        }
        __syncthreads();
    }

    float* base = &g_part[(size_t)ksplit * BATCH * NPAD];
#pragma unroll
    for (int mt = 0; mt < 4; mt++) {
#pragma unroll
        for (int nt = 0; nt < 4; nt++) {
            int m = mt * 16 + g;
            int n = n0 + wid * 32 + nt * 8 + 2 * t;
            float* a = acc[mt * 4 + nt];
            *(float2*)&base[(size_t)m * NPAD + n] = make_float2(a[0], a[1]);
            *(float2*)&base[(size_t)(m + 8) * NPAD + n] = make_float2(a[2], a[3]);
        }
    }
}

// ---------------------------------------------------------------------------
// Kernel 4: reduce
// ---------------------------------------------------------------------------
__global__ void k_reduce(float* __restrict__ out, const float* __restrict__ b2) {
    int idx = blockIdx.x * blockDim.x + threadIdx.x;
    if (idx >= BATCH * NCLS) return;
    int b = idx / NCLS, n = idx % NCLS;
    float acc = b2[n];
#pragma unroll
    for (int s = 0; s < KSPLITS; s++)
        acc += g_part[((size_t)s * BATCH + b) * NPAD + n];
    out[idx] = acc;
}

// ---------------------------------------------------------------------------
typedef CUresult (*PFN_encode_t)(CUtensorMap*, CUtensorMapDataType, cuuint32_t, void*,
                                 const cuuint64_t*, const cuuint64_t*, const cuuint32_t*,
                                 const cuuint32_t*, CUtensorMapInterleave, CUtensorMapSwizzle,
                                 CUtensorMapL2promotion, CUtensorMapFloatOOBfill);

extern "C" void kernel_launch(void* const* d_in, const int* in_sizes, int n_in,
                              void* d_out, int out_size) {
    const float* topview = (const float*)d_in[0];
    const float* search  = (const float*)d_in[1];
    const float* w1      = (const float*)d_in[2];
    const float* b1      = (const float*)d_in[3];
    const float* w2      = (const float*)d_in[4];
    const float* b2      = (const float*)d_in[5];
    float* out = (float*)d_out;

    void* fn = nullptr;
    cudaDriverEntryPointQueryResult qr;
#if CUDART_VERSION >= 12050
    cudaGetDriverEntryPointByVersion("cuTensorMapEncodeTiled", &fn, 12000,
                                     cudaEnableDefault, &qr);
#else
    cudaGetDriverEntryPoint("cuTensorMapEncodeTiled", &fn, cudaEnableDefault, &qr);
#endif
    PFN_encode_t encode = (PFN_encode_t)fn;

    CUtensorMap tmB;
    {
        cuuint64_t dims[2]    = {NCLS, KDIM};
        cuuint64_t strides[1] = {(cuuint64_t)NCLS * sizeof(float)};
        cuuint32_t box[2]     = {32, 32};
        cuuint32_t es[2]      = {1, 1};
        encode(&tmB, CU_TENSOR_MAP_DATA_TYPE_FLOAT32, 2, (void*)w2, dims, strides, box, es,
               CU_TENSOR_MAP_INTERLEAVE_NONE, CU_TENSOR_MAP_SWIZZLE_128B,
               CU_TENSOR_MAP_L2_PROMOTION_L2_128B, CU_TENSOR_MAP_FLOAT_OOB_FILL_NONE);
    }

    cudaFuncSetAttribute(k_gemm, cudaFuncAttributeMaxDynamicSharedMemorySize, SMEM_DYN);

    k_dummy<<<1, 32>>>();                                   // pos 0
    k_tv<<<BATCH, 48>>>(topview);                           // pos 1
    k_coords2<<<16, 256>>>(w1, b1);                         // pos 2
    k_gather<<<BATCH * (NPTS / GPTS), 256>>>(search);       // pos 3 (profiled)
    k_gemm<<<dim3(4, KSPLITS), 256, SMEM_DYN>>>(tmB);       // pos 4
    k_reduce<<<(BATCH * NCLS + 255) / 256, 256>>>(out, b2); // pos 5
}

// round 12
// speedup vs baseline: 1.9653x; 1.0651x over previous
#include <cuda_runtime.h>
#include <cuda.h>
#include <cuda_fp16.h>
#include <cstdint>
#include <math.h>

#define BATCH 64
#define NPTS 2048
#define KDIM 98304            // 2048*48
#define NCLS 1000
#define NPAD 1024
#define KSPLITS 64
#define KSP (KDIM / KSPLITS)  // 1536
#define KB 32                 // K per stage
#define STAGES_PER_CTA (KSP / KB)  // 48
#define TN 256
#define NSTAGES 2

#define B_SLAB 4096                          // 32 k-rows x 128B (fp32, SW128)
#define B_BYTES (8 * B_SLAB)                 // 32768
#define A_SLOT 1056                          // 64 rows x 16B + 32B pad (bank-clean)
#define A_BYTES (4 * A_SLOT)                 // 4224
#define STAGE_BYTES 37888                    // padded
#define SMEM_DYN (NSTAGES * STAGE_BYTES + 1024)

// ------------------------- device scratch -------------------------
__device__ float g_tv[BATCH * 48];
__device__ float g_xy[BATCH * NPTS * 2];
__device__ __align__(16) __half g_Ph[(size_t)BATCH * KDIM];  // fp16, k-permuted
__device__ float g_part[(size_t)KSPLITS * BATCH * NPAD];

// ------------------------- helpers -------------------------
__device__ __forceinline__ uint32_t smem_u32(const void* p) {
    uint32_t a;
    asm("{ .reg .u64 t; cvta.to.shared.u64 t, %1; cvt.u32.u64 %0, t; }" : "=r"(a) : "l"(p));
    return a;
}
__device__ __forceinline__ void cp_async16(uint32_t dst, const void* src) {
    asm volatile("cp.async.cg.shared.global [%0], [%1], 16;" :: "r"(dst), "l"(src) : "memory");
}
__device__ __forceinline__ void cp_commit() { asm volatile("cp.async.commit_group;" ::: "memory"); }
__device__ __forceinline__ void cp_wait1()  { asm volatile("cp.async.wait_group 1;" ::: "memory"); }
#define MBAR_INIT(addr, cnt) \
    asm volatile("mbarrier.init.shared.b64 [%0], %1;" :: "r"(addr), "r"(cnt) : "memory")
#define MBAR_EXPECT_TX(addr, bytes) \
    asm volatile("mbarrier.arrive.expect_tx.shared.b64 _, [%0], %1;" :: "r"(addr), "r"(bytes) : "memory")
#define MBAR_WAIT(addr, parity) do { \
    uint32_t _m = (addr), _p = (parity), _d; \
    asm volatile("{\n\t.reg .pred p;\n\tmbarrier.try_wait.parity.acquire.cta.shared::cta.b64 p, [%1], %2;\n\tselp.b32 %0,1,0,p;\n\t}" \
        : "=r"(_d) : "r"(_m), "r"(_p) : "memory"); \
    if (!_d) { \
        asm volatile("{\n\t.reg .pred P1;\n\tWL_%=:\n\tmbarrier.try_wait.parity.acquire.cta.shared::cta.b64 P1, [%0], %1, 0x989680;\n\t@P1 bra.uni WD_%=;\n\tbra.uni WL_%=;\n\tWD_%=:\n\t}" \
            :: "r"(_m), "r"(_p) : "memory"); \
    } \
} while (0)
#define TMA_LOAD_2D(smem, map, cx, cy, mbar) \
    asm volatile("cp.async.bulk.tensor.2d.shared::cta.global.tile.mbarrier::complete_tx::bytes [%0], [%1, {%2, %3}], [%4];" \
        :: "r"(smem), "l"(map), "r"(cx), "r"(cy), "r"(mbar) : "memory")

__device__ __forceinline__ uint32_t pack_f16x2(float lo, float hi) {
    uint32_t r;
    asm("cvt.rn.f16x2.f32 %0, %1, %2;" : "=r"(r) : "f"(hi), "f"(lo));
    return r;
}
__device__ __forceinline__ void mma_f16(float* c, uint32_t a0, uint32_t a1, uint32_t a2,
                                        uint32_t a3, uint32_t b0, uint32_t b1) {
    asm volatile(
        "mma.sync.aligned.m16n8k16.row.col.f32.f16.f16.f32 "
        "{%0,%1,%2,%3}, {%4,%5,%6,%7}, {%8,%9}, {%0,%1,%2,%3};"
        : "+f"(c[0]), "+f"(c[1]), "+f"(c[2]), "+f"(c[3])
        : "r"(a0), "r"(a1), "r"(a2), "r"(a3), "r"(b0), "r"(b1));
}

// ---------------------------------------------------------------------------
// Kernel 0: no-op (keeps gather at ncu capture position 3)
// ---------------------------------------------------------------------------
__global__ void k_dummy() {}

// ---------------------------------------------------------------------------
// Kernel 1a: tv resize (degenerate 4-pixel avg). 64 blocks x 48 threads.
// ---------------------------------------------------------------------------
__global__ void k_tv(const float* __restrict__ tv_img) {
    int b = blockIdx.x, d = threadIdx.x;
    int c = d / 16, rem = d % 16, i = rem / 4, j = rem % 4;
    const float* base = tv_img + ((size_t)(b * 3 + c)) * 64 * 64;
    int r0 = 16 * i + 7, c0 = 16 * j + 7;
    g_tv[b * 48 + d] = 0.25f * (base[r0 * 64 + c0] + base[r0 * 64 + c0 + 1] +
                                base[(r0 + 1) * 64 + c0] + base[(r0 + 1) * 64 + c0 + 1]);
}

// ---------------------------------------------------------------------------
// Kernel 1b: coords. 16 CTAs x 256 thr; w1 column per thread, all batches.
// ---------------------------------------------------------------------------
__global__ void __launch_bounds__(256) k_coords2(const float* __restrict__ w1,
                                                 const float* __restrict__ b1) {
    __shared__ float tv_s[BATCH * 48];
    int tid = threadIdx.x;
    int m = blockIdx.x * 256 + tid;
#pragma unroll
    for (int i = 0; i < 12; i++)
        tv_s[tid + i * 256] = g_tv[tid + i * 256];
    __syncthreads();

    float wcol[48];
#pragma unroll
    for (int d = 0; d < 48; d++) wcol[d] = w1[d * 4096 + m];
    float bias = b1[m];
    int p = m >> 1, q = m & 1;

    for (int b = 0; b < BATCH; b++) {
        const float* tvb = &tv_s[b * 48];
        float acc = bias;
#pragma unroll
        for (int d = 0; d < 48; d++) acc += wcol[d] * tvb[d];
        float s = 1.0f / (1.0f + expf(-acc));
        g_xy[(b * NPTS + p) * 2 + q] = s * 1019.0f + 2.0f;
    }
}

// ---------------------------------------------------------------------------
// Kernel 2: gather, division-free. 256 thr = 16 points x 16 slots.
// Phase 1: slot f<15 loads column f of the 5x15 region (5 loads, no div).
// Phase 2: slot ij computes its (i,j) tap, all 3 channels (two 6-float runs).
// Output fp16, k-permuted: r=off&15, kb=off>>4 -> pos=t*8+kb*4+pair*2+elem
// ---------------------------------------------------------------------------
#define GPTS 16
__global__ void __launch_bounds__(256) k_gather(const float* __restrict__ img) {
    __shared__ float px[GPTS][5][16];
    __shared__ float sfx[GPTS], sfy[GPTS];
    __shared__ int   sbase[GPTS];

    const int tid = threadIdx.x;
    const int g = tid >> 4;          // point 0..15
    const int f = tid & 15;          // slot 0..15
    const int b  = blockIdx.x >> 7;              // / (NPTS/GPTS) = /128
    const int p0 = (blockIdx.x & 127) << 4;      // * GPTS

    if (tid < GPTS) {
        int p = p0 + tid;
        float2 xy = *(const float2*)&g_xy[(b * NPTS + p) * 2];
        float x0 = floorf(xy.x), y0 = floorf(xy.y);
        sfx[tid] = xy.x - x0;
        sfy[tid] = xy.y - y0;
        sbase[tid] = (((int)x0 - 2) << 10 | 0) * 3 + ((int)y0 - 2) * 3;  // (r0*1024 + c0)*3
    }
    __syncthreads();

    const float* ib = img + (size_t)b * (1024u * 1024u * 3u);
    if (f < 15) {
        const float* src = ib + sbase[g] + f;
#pragma unroll
        for (int row = 0; row < 5; row++)
            px[g][row][f] = src[row * 3072];
    }
    __syncthreads();

    // phase 2: tap (i,j) = (f>>2, f&3); channels 0..2
    const int i = f >> 2, j = f & 3;
    float fx = sfx[g], fy = sfy[g];
    float w00 = (1.0f - fx) * (1.0f - fy);
    float w01 = (1.0f - fx) * fy;
    float w10 = fx * (1.0f - fy);
    float w11 = fx * fy;

    const float* r0 = &px[g][i][j * 3];      // [p00.0 p00.1 p00.2 p01.0 p01.1 p01.2]
    const float* r1 = &px[g][i + 1][j * 3];

    __half* rowp = &g_Ph[(size_t)b * KDIM];
    int kbase = (p0 + g) * 48 + f * 3;
#pragma unroll
    for (int ch = 0; ch < 3; ch++) {
        float v = r0[ch] * w00 + r0[ch + 3] * w01 + r1[ch] * w10 + r1[ch + 3] * w11;
        int k = kbase + ch;
        int off = k & 31;
        int r = off & 15, kb = off >> 4;
        int t = (r >> 1) & 3, pair = r >> 3, elem = r & 1;
        int pos = (t << 3) | (kb << 2) | (pair << 1) | elem;
        rowp[(k & ~31) | pos] = __float2half_rn(v);
    }
}

// ---------------------------------------------------------------------------
// Kernel 3: fp16 mma.sync m16n8k16 split-K GEMM (FROZEN from R10).
// ---------------------------------------------------------------------------
__global__ void __launch_bounds__(256, 2) k_gemm(const __grid_constant__ CUtensorMap tmB) {
    extern __shared__ __align__(16) char smem_raw[];
    __shared__ __align__(16) uint64_t mbar[NSTAGES];

    const int tid = threadIdx.x;
    const int wid = tid >> 5;
    const int lane = tid & 31;
    const int n0 = blockIdx.x * TN;
    const int ksplit = blockIdx.y;
    const int k0 = ksplit * KSP;
    const int g  = lane >> 2;
    const int t  = lane & 3;

    const uint32_t sbase = (smem_u32(smem_raw) + 1023u) & ~1023u;
    const uint32_t mb = smem_u32(mbar);

    if (tid == 0) { MBAR_INIT(mb, 1); MBAR_INIT(mb + 8, 1); }
    __syncthreads();

    auto issue_A = [&](int slot, int kofs) {
        uint32_t st = sbase + slot * STAGE_BYTES + B_BYTES;
        int row = tid & 63, c = tid >> 6;
        cp_async16(st + c * A_SLOT + row * 16,
                   &g_Ph[(size_t)row * KDIM + kofs + c * 8]);
        cp_commit();
    };
    auto issue_B = [&](int slot, int kofs) {
        if (tid == 0) {
            uint32_t full = mb + slot * 8;
            uint32_t bdst = sbase + slot * STAGE_BYTES;
            MBAR_EXPECT_TX(full, B_BYTES);
#pragma unroll
            for (int j = 0; j < 8; j++)
                TMA_LOAD_2D(bdst + j * B_SLAB, &tmB, n0 + 32 * j, kofs, full);
        }
    };

    issue_B(0, k0);
    issue_A(0, k0);

    float acc[16][4];
#pragma unroll
    for (int j = 0; j < 16; j++)
#pragma unroll
        for (int r = 0; r < 4; r++) acc[j][r] = 0.0f;

    uint32_t col0[4], col1[4];
#pragma unroll
    for (int nt = 0; nt < 4; nt++) {
        uint32_t n = nt * 8 + g;
        uint32_t chunk = n >> 2, e = (n & 3) * 4;
        col0[nt] = ((chunk ^ (uint32_t)(2 * t)) << 4) + e;
        col1[nt] = ((chunk ^ (uint32_t)(2 * t + 1)) << 4) + e;
    }

    for (int s = 0; s < STAGES_PER_CTA; s++) {
        int sn = s + 1;
        if (sn < STAGES_PER_CTA) { issue_B(sn & 1, k0 + sn * KB); issue_A(sn & 1, k0 + sn * KB); }
        else cp_commit();
        cp_wait1();
        MBAR_WAIT(mb + (s & 1) * 8, (s >> 1) & 1);
        __syncthreads();

        uint32_t st = sbase + (s & 1) * STAGE_BYTES;
        uint32_t abase = st + B_BYTES + t * A_SLOT;
        uint32_t bslab = st + wid * B_SLAB;

        uint4 av[8];
#pragma unroll
        for (int jr = 0; jr < 8; jr++) {
            asm volatile("ld.shared.v4.u32 {%0,%1,%2,%3}, [%4];"
                : "=r"(av[jr].x), "=r"(av[jr].y), "=r"(av[jr].z), "=r"(av[jr].w)
                : "r"(abase + (jr * 8 + g) * 16));
        }

#pragma unroll
        for (int kb = 0; kb < 2; kb++) {
            uint32_t rb0 = bslab + (kb * 16 + 2 * t) * 128;
            uint32_t rb1 = rb0 + 128;
#pragma unroll
            for (int nt = 0; nt < 4; nt++) {
                float v00, v01, v10, v11;
                asm volatile("ld.shared.f32 %0, [%1];" : "=f"(v00) : "r"(rb0 + col0[nt]));
                asm volatile("ld.shared.f32 %0, [%1];" : "=f"(v01) : "r"(rb1 + col1[nt]));
                asm volatile("ld.shared.f32 %0, [%1];" : "=f"(v10) : "r"(rb0 + 1024 + col0[nt]));
                asm volatile("ld.shared.f32 %0, [%1];" : "=f"(v11) : "r"(rb1 + 1024 + col1[nt]));
                uint32_t b0 = pack_f16x2(v00, v01);
                uint32_t b1 = pack_f16x2(v10, v11);
#pragma unroll
                for (int mt = 0; mt < 4; mt++) {
                    uint32_t a0 = kb ? av[2 * mt].z     : av[2 * mt].x;
                    uint32_t a2 = kb ? av[2 * mt].w     : av[2 * mt].y;
                    uint32_t a1 = kb ? av[2 * mt + 1].z : av[2 * mt + 1].x;
                    uint32_t a3 = kb ? av[2 * mt + 1].w : av[2 * mt + 1].y;
                    mma_f16(acc[mt * 4 + nt], a0, a1, a2, a3, b0, b1);
                }
            }
        }
        __syncthreads();
    }

    float* base = &g_part[(size_t)ksplit * BATCH * NPAD];
#pragma unroll
    for (int mt = 0; mt < 4; mt++) {
#pragma unroll
        for (int nt = 0; nt < 4; nt++) {
            int m = mt * 16 + g;
            int n = n0 + wid * 32 + nt * 8 + 2 * t;
            float* a = acc[mt * 4 + nt];
            *(float2*)&base[(size_t)m * NPAD + n] = make_float2(a[0], a[1]);
            *(float2*)&base[(size_t)(m + 8) * NPAD + n] = make_float2(a[2], a[3]);
        }
    }
}

// ---------------------------------------------------------------------------
// Kernel 4: reduce
// ---------------------------------------------------------------------------
__global__ void k_reduce(float* __restrict__ out, const float* __restrict__ b2) {
    int idx = blockIdx.x * blockDim.x + threadIdx.x;
    if (idx >= BATCH * NCLS) return;
    int b = idx / NCLS, n = idx % NCLS;
    float acc = b2[n];
#pragma unroll
    for (int s = 0; s < KSPLITS; s++)
        acc += g_part[((size_t)s * BATCH + b) * NPAD + n];
    out[idx] = acc;
}

// ---------------------------------------------------------------------------
typedef CUresult (*PFN_encode_t)(CUtensorMap*, CUtensorMapDataType, cuuint32_t, void*,
                                 const cuuint64_t*, const cuuint64_t*, const cuuint32_t*,
                                 const cuuint32_t*, CUtensorMapInterleave, CUtensorMapSwizzle,
                                 CUtensorMapL2promotion, CUtensorMapFloatOOBfill);

extern "C" void kernel_launch(void* const* d_in, const int* in_sizes, int n_in,
                              void* d_out, int out_size) {
    const float* topview = (const float*)d_in[0];
    const float* search  = (const float*)d_in[1];
    const float* w1      = (const float*)d_in[2];
    const float* b1      = (const float*)d_in[3];
    const float* w2      = (const float*)d_in[4];
    const float* b2      = (const float*)d_in[5];
    float* out = (float*)d_out;

    void* fn = nullptr;
    cudaDriverEntryPointQueryResult qr;
#if CUDART_VERSION >= 12050
    cudaGetDriverEntryPointByVersion("cuTensorMapEncodeTiled", &fn, 12000,
                                     cudaEnableDefault, &qr);
#else
    cudaGetDriverEntryPoint("cuTensorMapEncodeTiled", &fn, cudaEnableDefault, &qr);
#endif
    PFN_encode_t encode = (PFN_encode_t)fn;

    CUtensorMap tmB;
    {
        cuuint64_t dims[2]    = {NCLS, KDIM};
        cuuint64_t strides[1] = {(cuuint64_t)NCLS * sizeof(float)};
        cuuint32_t box[2]     = {32, 32};
        cuuint32_t es[2]      = {1, 1};
        encode(&tmB, CU_TENSOR_MAP_DATA_TYPE_FLOAT32, 2, (void*)w2, dims, strides, box, es,
               CU_TENSOR_MAP_INTERLEAVE_NONE, CU_TENSOR_MAP_SWIZZLE_128B,
               CU_TENSOR_MAP_L2_PROMOTION_L2_128B, CU_TENSOR_MAP_FLOAT_OOB_FILL_NONE);
    }

    cudaFuncSetAttribute(k_gemm, cudaFuncAttributeMaxDynamicSharedMemorySize, SMEM_DYN);

    k_dummy<<<1, 32>>>();                                   // pos 0
    k_tv<<<BATCH, 48>>>(topview);                           // pos 1
    k_coords2<<<16, 256>>>(w1, b1);                         // pos 2
    k_gather<<<BATCH * (NPTS / GPTS), 256>>>(search);       // pos 3 (profiled)
    k_gemm<<<dim3(4, KSPLITS), 256, SMEM_DYN>>>(tmB);       // pos 4
    k_reduce<<<(BATCH * NCLS + 255) / 256, 256>>>(out, b2); // pos 5
}

// round 13
// speedup vs baseline: 2.0052x; 1.0203x over previous
#include <cuda_runtime.h>
#include <cuda.h>
#include <cuda_fp16.h>
#include <cstdint>
#include <math.h>

#define BATCH 64
#define NPTS 2048
#define KDIM 98304            // 2048*48
#define NCLS 1000
#define NPAD 1024
#define KSPLITS 64
#define KSP (KDIM / KSPLITS)  // 1536
#define KB 32                 // K per stage
#define STAGES_PER_CTA (KSP / KB)  // 48
#define TN 256
#define NSTAGES 3

#define B_SLAB 4096                          // 32 k-rows x 128B (fp32, SW128)
#define B_BYTES (8 * B_SLAB)                 // 32768
#define A_SLOT 1056                          // 64 rows x 16B + 32B pad
#define A_BYTES (4 * A_SLOT)                 // 4224
#define STAGE_BYTES 37888                    // 37*1024 (keeps every stage 1024-aligned)
#define SMEM_DYN (NSTAGES * STAGE_BYTES + 1024)   // 114688

// ------------------------- device scratch -------------------------
__device__ float g_tv[BATCH * 48];
__device__ float g_xy[BATCH * NPTS * 2];
__device__ __align__(16) __half g_Ph[(size_t)BATCH * KDIM];  // fp16, k-permuted
__device__ float g_part[(size_t)KSPLITS * BATCH * NPAD];

// ------------------------- helpers -------------------------
__device__ __forceinline__ uint32_t smem_u32(const void* p) {
    uint32_t a;
    asm("{ .reg .u64 t; cvta.to.shared.u64 t, %1; cvt.u32.u64 %0, t; }" : "=r"(a) : "l"(p));
    return a;
}
__device__ __forceinline__ void cp_async16(uint32_t dst, const void* src) {
    asm volatile("cp.async.cg.shared.global [%0], [%1], 16;" :: "r"(dst), "l"(src) : "memory");
}
__device__ __forceinline__ void cp_commit() { asm volatile("cp.async.commit_group;" ::: "memory"); }
__device__ __forceinline__ void cp_wait2()  { asm volatile("cp.async.wait_group 2;" ::: "memory"); }
#define MBAR_INIT(addr, cnt) \
    asm volatile("mbarrier.init.shared.b64 [%0], %1;" :: "r"(addr), "r"(cnt) : "memory")
#define MBAR_EXPECT_TX(addr, bytes) \
    asm volatile("mbarrier.arrive.expect_tx.shared.b64 _, [%0], %1;" :: "r"(addr), "r"(bytes) : "memory")
#define MBAR_WAIT(addr, parity) do { \
    uint32_t _m = (addr), _p = (parity), _d; \
    asm volatile("{\n\t.reg .pred p;\n\tmbarrier.try_wait.parity.acquire.cta.shared::cta.b64 p, [%1], %2;\n\tselp.b32 %0,1,0,p;\n\t}" \
        : "=r"(_d) : "r"(_m), "r"(_p) : "memory"); \
    if (!_d) { \
        asm volatile("{\n\t.reg .pred P1;\n\tWL_%=:\n\tmbarrier.try_wait.parity.acquire.cta.shared::cta.b64 P1, [%0], %1, 0x989680;\n\t@P1 bra.uni WD_%=;\n\tbra.uni WL_%=;\n\tWD_%=:\n\t}" \
            :: "r"(_m), "r"(_p) : "memory"); \
    } \
} while (0)
#define TMA_LOAD_2D(smem, map, cx, cy, mbar) \
    asm volatile("cp.async.bulk.tensor.2d.shared::cta.global.tile.mbarrier::complete_tx::bytes [%0], [%1, {%2, %3}], [%4];" \
        :: "r"(smem), "l"(map), "r"(cx), "r"(cy), "r"(mbar) : "memory")

__device__ __forceinline__ uint32_t pack_f16x2(float lo, float hi) {
    uint32_t r;
    asm("cvt.rn.f16x2.f32 %0, %1, %2;" : "=r"(r) : "f"(hi), "f"(lo));
    return r;
}
__device__ __forceinline__ void mma_f16(float* c, uint32_t a0, uint32_t a1, uint32_t a2,
                                        uint32_t a3, uint32_t b0, uint32_t b1) {
    asm volatile(
        "mma.sync.aligned.m16n8k16.row.col.f32.f16.f16.f32 "
        "{%0,%1,%2,%3}, {%4,%5,%6,%7}, {%8,%9}, {%0,%1,%2,%3};"
        : "+f"(c[0]), "+f"(c[1]), "+f"(c[2]), "+f"(c[3])
        : "r"(a0), "r"(a1), "r"(a2), "r"(a3), "r"(b0), "r"(b1));
}

// ---------------------------------------------------------------------------
// Kernel 1a: tv resize (degenerate 4-pixel avg). 64 blocks x 48 threads.
// ---------------------------------------------------------------------------
__global__ void k_tv(const float* __restrict__ tv_img) {
    int b = blockIdx.x, d = threadIdx.x;
    int c = d / 16, rem = d % 16, i = rem / 4, j = rem % 4;
    const float* base = tv_img + ((size_t)(b * 3 + c)) * 64 * 64;
    int r0 = 16 * i + 7, c0 = 16 * j + 7;
    g_tv[b * 48 + d] = 0.25f * (base[r0 * 64 + c0] + base[r0 * 64 + c0 + 1] +
                                base[(r0 + 1) * 64 + c0] + base[(r0 + 1) * 64 + c0 + 1]);
}

// ---------------------------------------------------------------------------
// Kernel 1b: coords. 16 CTAs x 256 thr; w1 column per thread, all batches.
// ---------------------------------------------------------------------------
__global__ void __launch_bounds__(256) k_coords2(const float* __restrict__ w1,
                                                 const float* __restrict__ b1) {
    __shared__ float tv_s[BATCH * 48];
    int tid = threadIdx.x;
    int m = blockIdx.x * 256 + tid;
#pragma unroll
    for (int i = 0; i < 12; i++)
        tv_s[tid + i * 256] = g_tv[tid + i * 256];
    __syncthreads();

    float wcol[48];
#pragma unroll
    for (int d = 0; d < 48; d++) wcol[d] = w1[d * 4096 + m];
    float bias = b1[m];
    int p = m >> 1, q = m & 1;

    for (int b = 0; b < BATCH; b++) {
        const float* tvb = &tv_s[b * 48];
        float acc = bias;
#pragma unroll
        for (int d = 0; d < 48; d++) acc += wcol[d] * tvb[d];
        float s = 1.0f / (1.0f + expf(-acc));
        g_xy[(b * NPTS + p) * 2 + q] = s * 1019.0f + 2.0f;
    }
}

// ---------------------------------------------------------------------------
// Kernel 2: gather, division-free, SMEM-staged output (coalesced float4 STG).
// CTA output region [p0*48, p0*48+768) halves is 32-block aligned.
// ---------------------------------------------------------------------------
#define GPTS 16
__global__ void __launch_bounds__(256) k_gather(const float* __restrict__ img) {
    __shared__ float px[GPTS][5][16];
    __shared__ float sfx[GPTS], sfy[GPTS];
    __shared__ int   sbase[GPTS];
    __shared__ __align__(16) __half sh_out[GPTS * 48];   // 1536 B

    const int tid = threadIdx.x;
    const int g = tid >> 4;          // point 0..15
    const int f = tid & 15;          // slot 0..15
    const int b  = blockIdx.x >> 7;
    const int p0 = (blockIdx.x & 127) << 4;

    if (tid < GPTS) {
        int p = p0 + tid;
        float2 xy = *(const float2*)&g_xy[(b * NPTS + p) * 2];
        float x0 = floorf(xy.x), y0 = floorf(xy.y);
        sfx[tid] = xy.x - x0;
        sfy[tid] = xy.y - y0;
        sbase[tid] = (((int)x0 - 2) << 10) * 3 + ((int)y0 - 2) * 3;
    }
    __syncthreads();

    const float* ib = img + (size_t)b * (1024u * 1024u * 3u);
    if (f < 15) {
        const float* src = ib + sbase[g] + f;
#pragma unroll
        for (int row = 0; row < 5; row++)
            px[g][row][f] = src[row * 3072];
    }
    __syncthreads();

    const int i = f >> 2, j = f & 3;
    float fx = sfx[g], fy = sfy[g];
    float w00 = (1.0f - fx) * (1.0f - fy);
    float w01 = (1.0f - fx) * fy;
    float w10 = fx * (1.0f - fy);
    float w11 = fx * fy;

    const float* r0 = &px[g][i][j * 3];
    const float* r1 = &px[g][i + 1][j * 3];

    int kloc = g * 48 + f * 3;    // local k within the aligned 768-half region
#pragma unroll
    for (int ch = 0; ch < 3; ch++) {
        float v = r0[ch] * w00 + r0[ch + 3] * w01 + r1[ch] * w10 + r1[ch + 3] * w11;
        int k = kloc + ch;
        int off = k & 31;
        int r = off & 15, kb = off >> 4;
        int t = (r >> 1) & 3, pair = r >> 3, elem = r & 1;
        int pos = (t << 3) | (kb << 2) | (pair << 1) | elem;
        sh_out[(k & ~31) | pos] = __float2half_rn(v);
    }
    __syncthreads();

    // coalesced writeout: 768 halves = 96 float4
    if (tid < 96) {
        float4 v4 = *(const float4*)&sh_out[tid * 8];
        *(float4*)&g_Ph[(size_t)b * KDIM + p0 * 48 + tid * 8] = v4;
    }
}

// ---------------------------------------------------------------------------
// Kernel 3: fp16 mma.sync m16n8k16 split-K GEMM, 3-stage pipeline (lag-2).
// ---------------------------------------------------------------------------
__global__ void __launch_bounds__(256, 2) k_gemm(const __grid_constant__ CUtensorMap tmB) {
    extern __shared__ __align__(16) char smem_raw[];
    __shared__ __align__(16) uint64_t mbar[NSTAGES];

    const int tid = threadIdx.x;
    const int wid = tid >> 5;
    const int lane = tid & 31;
    const int n0 = blockIdx.x * TN;
    const int ksplit = blockIdx.y;
    const int k0 = ksplit * KSP;
    const int g  = lane >> 2;
    const int t  = lane & 3;

    const uint32_t sbase = (smem_u32(smem_raw) + 1023u) & ~1023u;
    const uint32_t mb = smem_u32(mbar);

    if (tid == 0) {
#pragma unroll
        for (int s = 0; s < NSTAGES; s++) MBAR_INIT(mb + s * 8, 1);
    }
    __syncthreads();

    auto issue_A = [&](int slot, int kofs) {
        uint32_t st = sbase + slot * STAGE_BYTES + B_BYTES;
        int row = tid & 63, c = tid >> 6;
        cp_async16(st + c * A_SLOT + row * 16,
                   &g_Ph[(size_t)row * KDIM + kofs + c * 8]);
        cp_commit();
    };
    auto issue_B = [&](int slot, int kofs) {
        if (tid == 0) {
            uint32_t full = mb + slot * 8;
            uint32_t bdst = sbase + slot * STAGE_BYTES;
            MBAR_EXPECT_TX(full, B_BYTES);
#pragma unroll
            for (int j = 0; j < 8; j++)
                TMA_LOAD_2D(bdst + j * B_SLAB, &tmB, n0 + 32 * j, kofs, full);
        }
    };

    // prologue: stages 0 and 1
    issue_B(0, k0);           issue_A(0, k0);
    issue_B(1, k0 + KB);      issue_A(1, k0 + KB);

    float acc[16][4];
#pragma unroll
    for (int j = 0; j < 16; j++)
#pragma unroll
        for (int r = 0; r < 4; r++) acc[j][r] = 0.0f;

    uint32_t col0[4], col1[4];
#pragma unroll
    for (int nt = 0; nt < 4; nt++) {
        uint32_t n = nt * 8 + g;
        uint32_t chunk = n >> 2, e = (n & 3) * 4;
        col0[nt] = ((chunk ^ (uint32_t)(2 * t)) << 4) + e;
        col1[nt] = ((chunk ^ (uint32_t)(2 * t + 1)) << 4) + e;
    }

    int slot = 0, phase = 0;        // consumer cursor
    int pslot = 2;                  // producer slot for stage s+2
    for (int s = 0; s < STAGES_PER_CTA; s++) {
        int sn = s + 2;
        if (sn < STAGES_PER_CTA) {
            issue_B(pslot, k0 + sn * KB);
            issue_A(pslot, k0 + sn * KB);
        } else cp_commit();          // keep one commit per iter for wait_group math
        if (++pslot == NSTAGES) pslot = 0;

        cp_wait2();                  // A of stage s complete (<=2 groups outstanding)
        MBAR_WAIT(mb + slot * 8, phase);
        __syncthreads();

        uint32_t st = sbase + slot * STAGE_BYTES;
        uint32_t abase = st + B_BYTES + t * A_SLOT;
        uint32_t bslab = st + wid * B_SLAB;

        uint4 av[8];
#pragma unroll
        for (int jr = 0; jr < 8; jr++) {
            asm volatile("ld.shared.v4.u32 {%0,%1,%2,%3}, [%4];"
                : "=r"(av[jr].x), "=r"(av[jr].y), "=r"(av[jr].z), "=r"(av[jr].w)
                : "r"(abase + (jr * 8 + g) * 16));
        }

#pragma unroll
        for (int kb = 0; kb < 2; kb++) {
            uint32_t rb0 = bslab + (kb * 16 + 2 * t) * 128;
            uint32_t rb1 = rb0 + 128;
#pragma unroll
            for (int nt = 0; nt < 4; nt++) {
                float v00, v01, v10, v11;
                asm volatile("ld.shared.f32 %0, [%1];" : "=f"(v00) : "r"(rb0 + col0[nt]));
                asm volatile("ld.shared.f32 %0, [%1];" : "=f"(v01) : "r"(rb1 + col1[nt]));
                asm volatile("ld.shared.f32 %0, [%1];" : "=f"(v10) : "r"(rb0 + 1024 + col0[nt]));
                asm volatile("ld.shared.f32 %0, [%1];" : "=f"(v11) : "r"(rb1 + 1024 + col1[nt]));
                uint32_t b0 = pack_f16x2(v00, v01);
                uint32_t b1 = pack_f16x2(v10, v11);
#pragma unroll
                for (int mt = 0; mt < 4; mt++) {
                    uint32_t a0 = kb ? av[2 * mt].z     : av[2 * mt].x;
                    uint32_t a2 = kb ? av[2 * mt].w     : av[2 * mt].y;
                    uint32_t a1 = kb ? av[2 * mt + 1].z : av[2 * mt + 1].x;
                    uint32_t a3 = kb ? av[2 * mt + 1].w : av[2 * mt + 1].y;
                    mma_f16(acc[mt * 4 + nt], a0, a1, a2, a3, b0, b1);
                }
            }
        }
        __syncthreads();
        if (++slot == NSTAGES) { slot = 0; phase ^= 1; }
    }

    float* base = &g_part[(size_t)ksplit * BATCH * NPAD];
#pragma unroll
    for (int mt = 0; mt < 4; mt++) {
#pragma unroll
        for (int nt = 0; nt < 4; nt++) {
            int m = mt * 16 + g;
            int n = n0 + wid * 32 + nt * 8 + 2 * t;
            float* a = acc[mt * 4 + nt];
            *(float2*)&base[(size_t)m * NPAD + n] = make_float2(a[0], a[1]);
            *(float2*)&base[(size_t)(m + 8) * NPAD + n] = make_float2(a[2], a[3]);
        }
    }
}

// ---------------------------------------------------------------------------
// Kernel 4: reduce
// ---------------------------------------------------------------------------
__global__ void k_reduce(float* __restrict__ out, const float* __restrict__ b2) {
    int idx = blockIdx.x * blockDim.x + threadIdx.x;
    if (idx >= BATCH * NCLS) return;
    int b = idx / NCLS, n = idx % NCLS;
    float acc = b2[n];
#pragma unroll
    for (int s = 0; s < KSPLITS; s++)
        acc += g_part[((size_t)s * BATCH + b) * NPAD + n];
    out[idx] = acc;
}

// ---------------------------------------------------------------------------
typedef CUresult (*PFN_encode_t)(CUtensorMap*, CUtensorMapDataType, cuuint32_t, void*,
                                 const cuuint64_t*, const cuuint64_t*, const cuuint32_t*,
                                 const cuuint32_t*, CUtensorMapInterleave, CUtensorMapSwizzle,
                                 CUtensorMapL2promotion, CUtensorMapFloatOOBfill);

extern "C" void kernel_launch(void* const* d_in, const int* in_sizes, int n_in,
                              void* d_out, int out_size) {
    const float* topview = (const float*)d_in[0];
    const float* search  = (const float*)d_in[1];
    const float* w1      = (const float*)d_in[2];
    const float* b1      = (const float*)d_in[3];
    const float* w2      = (const float*)d_in[4];
    const float* b2      = (const float*)d_in[5];
    float* out = (float*)d_out;

    void* fn = nullptr;
    cudaDriverEntryPointQueryResult qr;
#if CUDART_VERSION >= 12050
    cudaGetDriverEntryPointByVersion("cuTensorMapEncodeTiled", &fn, 12000,
                                     cudaEnableDefault, &qr);
#else
    cudaGetDriverEntryPoint("cuTensorMapEncodeTiled", &fn, cudaEnableDefault, &qr);
#endif
    PFN_encode_t encode = (PFN_encode_t)fn;

    CUtensorMap tmB;
    {
        cuuint64_t dims[2]    = {NCLS, KDIM};
        cuuint64_t strides[1] = {(cuuint64_t)NCLS * sizeof(float)};
        cuuint32_t box[2]     = {32, 32};
        cuuint32_t es[2]      = {1, 1};
        encode(&tmB, CU_TENSOR_MAP_DATA_TYPE_FLOAT32, 2, (void*)w2, dims, strides, box, es,
               CU_TENSOR_MAP_INTERLEAVE_NONE, CU_TENSOR_MAP_SWIZZLE_128B,
               CU_TENSOR_MAP_L2_PROMOTION_L2_128B, CU_TENSOR_MAP_FLOAT_OOB_FILL_NONE);
    }

    cudaFuncSetAttribute(k_gemm, cudaFuncAttributeMaxDynamicSharedMemorySize, SMEM_DYN);

    k_tv<<<BATCH, 48>>>(topview);                           // pos 0
    k_coords2<<<16, 256>>>(w1, b1);                         // pos 1
    k_gather<<<BATCH * (NPTS / GPTS), 256>>>(search);       // pos 2
    k_gemm<<<dim3(4, KSPLITS), 256, SMEM_DYN>>>(tmB);       // pos 3 (profiled)
    k_reduce<<<(BATCH * NCLS + 255) / 256, 256>>>(out, b2); // pos 4
}